// round 1
// baseline (speedup 1.0000x reference)
#include <cuda_runtime.h>

#define TLEN 8192
#define MH   4096
#define NF   4097
#define NHID 64
#define NCIN 32
#define NCOUT 32
#define NB   8

// ---------------- device global scratch (allocation-free) ----------------
__device__ float2 d_TW[MH];                    // e^{-2*pi*i*k/8192}, k<4096
__device__ float  d_H2T[NHID * TLEN];          // MLP hidden, transposed [j][t]
__device__ float2 d_Xf[(NB * NCIN) * NF];      // rfft(x) rows
__device__ float2 d_Ff[(NCOUT * NCIN) * NF];   // rfft(filters) rows
__device__ float2 d_Gf[(NB * NCOUT) * NF];     // contracted spectrum rows

__device__ __forceinline__ float2 cmulf(float2 a, float2 b) {
    return make_float2(fmaf(a.x, b.x, -a.y * b.y), fmaf(a.x, b.y, a.y * b.x));
}
__device__ __forceinline__ int brev12(int k) { return (int)(__brev((unsigned)k) >> 20); }

// ---------------- twiddle init (double precision, tiny) ----------------
__global__ void init_tw_kernel() {
    int k = blockIdx.x * blockDim.x + threadIdx.x;
    if (k < MH) {
        double a = -2.0 * 3.14159265358979323846 * (double)k / (double)TLEN;
        d_TW[k] = make_float2((float)cos(a), (float)sin(a));
    }
}

// ---------------- in-place radix-2 DIT FFT of 4096 complex in smem ----------------
// Input must be placed in bit-reversed order. Natural order output.
__device__ void fft4096(float2* buf, int tid, int nt) {
    for (int s = 0; s < 12; ++s) {
        __syncthreads();
        int hlf = 1 << s;
        for (int idx = tid; idx < MH / 2; idx += nt) {
            int grp = idx >> s;
            int pos = idx & (hlf - 1);
            int i0 = (grp << (s + 1)) + pos;
            int i1 = i0 + hlf;
            float2 w = d_TW[pos << (12 - s)];  // e^{-2pi i pos / 2^{s+1}}
            float2 a = buf[i0];
            float2 b = buf[i1];
            float2 t = cmulf(w, b);
            buf[i0] = make_float2(a.x + t.x, a.y + t.y);
            buf[i1] = make_float2(a.x - t.x, a.y - t.y);
        }
    }
    __syncthreads();
}

// rfft postprocess: buf = FFT_4096(x[2k] + i x[2k+1]) -> out[0..4096] = rfft_8192(x)
__device__ void rfft_post(const float2* buf, float2* out, int tid, int nt) {
    for (int k = tid; k <= MH / 2; k += nt) {
        float2 Zk = buf[k];
        float2 Zm = buf[(MH - k) & (MH - 1)];
        float2 E  = make_float2(0.5f * (Zk.x + Zm.x), 0.5f * (Zk.y - Zm.y));
        float2 O  = make_float2(0.5f * (Zk.y + Zm.y), 0.5f * (Zm.x - Zk.x));
        float2 W  = d_TW[k];
        float2 WO = cmulf(W, O);
        out[k]      = make_float2(E.x + WO.x, E.y + WO.y);
        out[MH - k] = make_float2(E.x - WO.x, -(E.y - WO.y));
    }
}

// ---------------- MLP hidden: H2T[j][t] = gelu(gelu(pos*w1+b1) @ w2 + b2) ----------------
__global__ void mlp_kernel(const float* __restrict__ w1, const float* __restrict__ b1,
                           const float* __restrict__ w2, const float* __restrict__ b2) {
    __shared__ float w2s[NHID * NHID];
    __shared__ float w1s[NHID], b1s[NHID], b2s[NHID];
    int tid = threadIdx.x;
    for (int i = tid; i < NHID * NHID; i += blockDim.x) w2s[i] = w2[i];
    if (tid < NHID) { w1s[tid] = w1[tid]; b1s[tid] = b1[tid]; b2s[tid] = b2[tid]; }
    __syncthreads();
    int t = blockIdx.x * blockDim.x + tid;
    float pos = (float)t / 8191.0f;
    float h1[NHID];
#pragma unroll
    for (int k = 0; k < NHID; k++) {
        float v = fmaf(pos, w1s[k], b1s[k]);
        h1[k] = 0.5f * v * (1.0f + erff(v * 0.70710678118654752f));
    }
    for (int j = 0; j < NHID; j++) {
        float acc = b2s[j];
#pragma unroll
        for (int k = 0; k < NHID; k++) acc = fmaf(h1[k], w2s[k * NHID + j], acc);
        float g = 0.5f * acc * (1.0f + erff(acc * 0.70710678118654752f));
        d_H2T[j * TLEN + t] = g;
    }
}

// ---------------- rfft of x rows ----------------
__global__ void rfft_x_kernel(const float* __restrict__ x) {
    __shared__ float2 buf[MH];
    int tid = threadIdx.x, nt = blockDim.x;
    int row = blockIdx.x;  // b*32+i
    const float2* xr = (const float2*)(x + (size_t)row * TLEN);
    for (int k = tid; k < MH; k += nt) buf[brev12(k)] = xr[k];
    fft4096(buf, tid, nt);
    rfft_post(buf, d_Xf + (size_t)row * NF, tid, nt);
}

// ---------------- filters: GEMM column + rfft, 4 columns per block ----------------
__global__ void filt_fft_kernel(const float* __restrict__ w3, const float* __restrict__ b3) {
    extern __shared__ float2 sm[];
    float2* bufs = sm;                        // 4 * 4096 float2 = 128 KB
    float*  wcol = (float*)(sm + 4 * MH);     // 64*4 floats
    float*  b3s  = wcol + 256;                // 4 floats
    int tid = threadIdx.x, nt = blockDim.x;
    int cbase = blockIdx.x * 4;               // column = o*32+i
    for (int idx = tid; idx < NHID * 4; idx += nt) {
        int k = idx >> 2, cc = idx & 3;
        wcol[idx] = w3[k * (NCIN * NCOUT) + cbase + cc];
    }
    if (tid < 4) b3s[tid] = b3[cbase + tid];
    __syncthreads();
    for (int k = tid; k < MH; k += nt) {
        float accE[4], accO[4];
#pragma unroll
        for (int cc = 0; cc < 4; cc++) { accE[cc] = b3s[cc]; accO[cc] = b3s[cc]; }
        int t0 = 2 * k;
        for (int j = 0; j < NHID; j++) {
            float h0 = d_H2T[j * TLEN + t0];
            float h1 = d_H2T[j * TLEN + t0 + 1];
#pragma unroll
            for (int cc = 0; cc < 4; cc++) {
                float w = wcol[j * 4 + cc];
                accE[cc] = fmaf(h0, w, accE[cc]);
                accO[cc] = fmaf(h1, w, accO[cc]);
            }
        }
        int kb = brev12(k);
#pragma unroll
        for (int cc = 0; cc < 4; cc++) bufs[cc * MH + kb] = make_float2(accE[cc], accO[cc]);
    }
    for (int cc = 0; cc < 4; cc++) {
        float2* buf = bufs + cc * MH;
        fft4096(buf, tid, nt);
        rfft_post(buf, d_Ff + (size_t)(cbase + cc) * NF, tid, nt);
        __syncthreads();
    }
}

// ---------------- frequency contraction: Gf[b,o,f] = sum_i Xf[b,i,f]*Ff[o,i,f] ----------------
__global__ void contract_kernel() {
    __shared__ float2 Xs[4 * 256];   // [fo][b*32+i], reused as output staging
    __shared__ float2 Fs[4 * 1024];  // [fo][i*32+o]
    int tid = threadIdx.x;
    int f0 = blockIdx.x * 4;
    for (int idx = tid; idx < 1024; idx += 256) {
        int row = idx >> 2, fo = idx & 3;
        int f = f0 + fo;
        Xs[fo * 256 + row] = (f < NF) ? d_Xf[(size_t)row * NF + f] : make_float2(0.f, 0.f);
    }
    for (int idx = tid; idx < 4096; idx += 256) {
        int oi = idx >> 2, fo = idx & 3;
        int f = f0 + fo;
        int o = oi >> 5, i = oi & 31;
        Fs[fo * 1024 + i * 32 + o] = (f < NF) ? d_Ff[(size_t)oi * NF + f] : make_float2(0.f, 0.f);
    }
    __syncthreads();
    int b = tid >> 5, o = tid & 31;
    float2 res[4];
#pragma unroll
    for (int fo = 0; fo < 4; fo++) {
        float2 acc = make_float2(0.f, 0.f);
        const float2* Xp = Xs + fo * 256 + b * 32;
        const float2* Fp = Fs + fo * 1024 + o;
#pragma unroll 8
        for (int i = 0; i < 32; i++) {
            float2 xv = Xp[i];
            float2 fv = Fp[i * 32];
            acc.x = fmaf(xv.x, fv.x, acc.x);
            acc.x = fmaf(-xv.y, fv.y, acc.x);
            acc.y = fmaf(xv.x, fv.y, acc.y);
            acc.y = fmaf(xv.y, fv.x, acc.y);
        }
        res[fo] = acc;
    }
    __syncthreads();
#pragma unroll
    for (int fo = 0; fo < 4; fo++) Xs[fo * 256 + tid] = res[fo];
    __syncthreads();
    for (int idx = tid; idx < 1024; idx += 256) {
        int row = idx >> 2, fo = idx & 3;
        int f = f0 + fo;
        if (f < NF) d_Gf[(size_t)row * NF + f] = Xs[fo * 256 + row];
    }
}

// ---------------- inverse rfft + bias ----------------
__global__ void irfft_kernel(const float* __restrict__ bias, float* __restrict__ out) {
    __shared__ float2 buf[MH];
    int tid = threadIdx.x, nt = blockDim.x;
    int row = blockIdx.x;  // b*32+o
    const float2* G = d_Gf + (size_t)row * NF;
    for (int k = tid; k < MH; k += nt) {
        float2 Xk = G[k];
        float2 Xm = G[MH - k];
        float2 E = make_float2(0.5f * (Xk.x + Xm.x), 0.5f * (Xk.y - Xm.y));
        float2 D = make_float2(0.5f * (Xk.x - Xm.x), 0.5f * (Xk.y + Xm.y));
        float2 Wc = d_TW[k];
        float2 Winv = make_float2(Wc.x, -Wc.y);  // e^{+2pi i k/8192}
        float2 O = cmulf(Winv, D);
        // Z = E + i*O ; store conj(Z) in bit-reversed slot
        buf[brev12(k)] = make_float2(E.x - O.y, -(E.y + O.x));
    }
    fft4096(buf, tid, nt);
    float bo = bias[row & 31];
    float2* orow = (float2*)(out + (size_t)row * TLEN);
    const float inv = 1.0f / (float)MH;
    for (int k = tid; k < MH; k += nt) {
        float2 z = buf[k];
        orow[k] = make_float2(fmaf(z.x, inv, bo), fmaf(-z.y, inv, bo));
    }
}

// ---------------- launch ----------------
extern "C" void kernel_launch(void* const* d_in, const int* in_sizes, int n_in,
                              void* d_out, int out_size) {
    const float* x    = (const float*)d_in[0];
    const float* w1   = (const float*)d_in[1];
    const float* b1   = (const float*)d_in[2];
    const float* w2   = (const float*)d_in[3];
    const float* b2   = (const float*)d_in[4];
    const float* w3   = (const float*)d_in[5];
    const float* b3   = (const float*)d_in[6];
    const float* bias = (const float*)d_in[7];
    float* out = (float*)d_out;

    size_t filt_smem = 4 * MH * sizeof(float2) + (256 + 4) * sizeof(float);
    cudaFuncSetAttribute(filt_fft_kernel, cudaFuncAttributeMaxDynamicSharedMemorySize,
                         (int)filt_smem);

    init_tw_kernel<<<8, 512>>>();
    mlp_kernel<<<TLEN / 128, 128>>>(w1, b1, w2, b2);
    rfft_x_kernel<<<NB * NCIN, 512>>>(x);
    filt_fft_kernel<<<(NCOUT * NCIN) / 4, 512, filt_smem>>>(w3, b3);
    contract_kernel<<<(NF + 3) / 4, 256>>>();
    irfft_kernel<<<NB * NCOUT, 512>>>(bias, out);
}

// round 3
// speedup vs baseline: 1.9437x; 1.9437x over previous
#include <cuda_runtime.h>

#define TLEN 8192
#define MH   4096
#define NF   4097
#define NHID 64
#define NCIN 32
#define NCOUT 32
#define NB   8

// ---------------- device global scratch (allocation-free) ----------------
__device__ float2 d_TW8[TLEN];                 // e^{-2*pi*i*k/8192}
__device__ float  d_H2T[NHID * TLEN];          // MLP hidden, transposed [j][t]
__device__ float  d_Filt[NCOUT * NCIN * TLEN]; // time-domain filters [col][t]
__device__ float2 d_Xf[(NB * NCIN) * NF];      // rfft(x) rows
__device__ float2 d_Ff[(NCOUT * NCIN) * NF];   // rfft(filters) rows
__device__ float2 d_Gf[(NB * NCOUT) * NF];     // contracted spectrum rows

__device__ __forceinline__ float2 cmulf(float2 a, float2 b) {
    return make_float2(fmaf(a.x, b.x, -a.y * b.y), fmaf(a.x, b.y, a.y * b.x));
}
__device__ __forceinline__ float2 cadd(float2 a, float2 b) { return make_float2(a.x + b.x, a.y + b.y); }
__device__ __forceinline__ float2 csub(float2 a, float2 b) { return make_float2(a.x - b.x, a.y - b.y); }
__device__ __forceinline__ float2 mulnegi(float2 a) { return make_float2(a.y, -a.x); }

#define PADIDX(a) ((a) + ((a) >> 3))

// ---------------- twiddle init (double precision, tiny) ----------------
__global__ void init_tw_kernel() {
    int k = blockIdx.x * blockDim.x + threadIdx.x;
    if (k < TLEN) {
        double a = -2.0 * 3.14159265358979323846 * (double)k / (double)TLEN;
        d_TW8[k] = make_float2((float)cos(a), (float)sin(a));
    }
}

// ---------------- 8-point DFT in registers ----------------
__device__ __forceinline__ void fft8(const float2 c[8], float2 d[8]) {
    const float S = 0.70710678118654752440f;
    float2 a0 = cadd(c[0], c[4]), a1 = cadd(c[1], c[5]);
    float2 a2 = cadd(c[2], c[6]), a3 = cadd(c[3], c[7]);
    float2 b0 = csub(c[0], c[4]);
    float2 t1 = csub(c[1], c[5]);
    float2 b1 = make_float2(S * (t1.x + t1.y), S * (t1.y - t1.x));   // * w8^1
    float2 t2 = csub(c[2], c[6]);
    float2 b2 = mulnegi(t2);                                          // * w8^2 = -i
    float2 t3 = csub(c[3], c[7]);
    float2 b3 = make_float2(S * (t3.y - t3.x), -S * (t3.x + t3.y));  // * w8^3
    float2 p0 = cadd(a0, a2), q0 = csub(a0, a2);
    float2 p1 = cadd(a1, a3), q1 = mulnegi(csub(a1, a3));
    d[0] = cadd(p0, p1); d[4] = csub(p0, p1);
    d[2] = cadd(q0, q1); d[6] = csub(q0, q1);
    float2 r0 = cadd(b0, b2), s0 = csub(b0, b2);
    float2 r1 = cadd(b1, b3), s1 = mulnegi(csub(b1, b3));
    d[1] = cadd(r0, r1); d[5] = csub(r0, r1);
    d[3] = cadd(s0, s1); d[7] = csub(s0, s1);
}

// ---------------- one radix-8 Stockham DIF stage ----------------
template <int L, int M, int SP, int DP>
__device__ __forceinline__ void stage8(const float2* __restrict__ src,
                                       float2* __restrict__ dst, int tid) {
    int j = tid / M;
    int k = tid - j * M;
    float2 c[8], d[8];
#pragma unroll
    for (int i = 0; i < 8; i++) {
        int a = tid + i * 512;
        c[i] = src[SP ? PADIDX(a) : a];
    }
    fft8(c, d);
    if (L > 1) {
        int tstep = j * (1024 / L);   // = 2*j*M  (e^{-2pi i * j*M*t/4096})
        float2 w = d_TW8[tstep];
        float2 wt = w;
        d[1] = cmulf(d[1], w);
#pragma unroll
        for (int t = 2; t < 8; t++) {
            wt = cmulf(wt, w);
            d[t] = cmulf(d[t], wt);
        }
    }
    int base = k + M * 8 * j;
#pragma unroll
    for (int t = 0; t < 8; t++) {
        int a = base + M * t;
        dst[DP ? PADIDX(a) : a] = d[t];
    }
}

// ---------------- full 4096-pt complex FFT (Stockham, natural in/out) ----------------
__device__ void fft4096(const float2* __restrict__ src, float2* A, float2* Bp, int tid) {
    stage8<512, 1, 0, 1>(src, Bp, tid);
    __syncthreads();
    stage8<64, 8, 1, 0>(Bp, A, tid);
    __syncthreads();
    stage8<8, 64, 0, 1>(A, Bp, tid);
    __syncthreads();
    stage8<1, 512, 1, 0>(Bp, A, tid);
    __syncthreads();
}

// rfft postprocess
__device__ void rfft_post(const float2* A, float2* out, int tid) {
    for (int k = tid; k <= MH / 2; k += 512) {
        float2 Zk = A[k];
        float2 Zm = A[(MH - k) & (MH - 1)];
        float2 E = make_float2(0.5f * (Zk.x + Zm.x), 0.5f * (Zk.y - Zm.y));
        float2 O = make_float2(0.5f * (Zk.y + Zm.y), 0.5f * (Zm.x - Zk.x));
        float2 WO = cmulf(d_TW8[k], O);
        out[k]      = make_float2(E.x + WO.x, E.y + WO.y);
        out[MH - k] = make_float2(E.x - WO.x, -(E.y - WO.y));
    }
}

__device__ void rfft_row(const float* __restrict__ src_row, float2* __restrict__ dst_row,
                         float2* A, float2* Bp, int tid) {
    const float2* xr = (const float2*)src_row;
    fft4096(xr, A, Bp, tid);
    rfft_post(A, dst_row, tid);
}

#define FFT_SMEM ((4096 + 4608) * sizeof(float2))

// ---------------- MLP hidden ----------------
__global__ void mlp_kernel(const float* __restrict__ w1, const float* __restrict__ b1,
                           const float* __restrict__ w2, const float* __restrict__ b2) {
    __shared__ float w2s[NHID * NHID];
    __shared__ float w1s[NHID], b1s[NHID], b2s[NHID];
    int tid = threadIdx.x;
    for (int i = tid; i < NHID * NHID; i += blockDim.x) w2s[i] = w2[i];
    if (tid < NHID) { w1s[tid] = w1[tid]; b1s[tid] = b1[tid]; b2s[tid] = b2[tid]; }
    __syncthreads();
    int t = blockIdx.x * blockDim.x + tid;
    float pos = (float)t / 8191.0f;
    float h1[NHID];
#pragma unroll
    for (int k = 0; k < NHID; k++) {
        float v = fmaf(pos, w1s[k], b1s[k]);
        h1[k] = 0.5f * v * (1.0f + erff(v * 0.70710678118654752f));
    }
    for (int j = 0; j < NHID; j++) {
        float acc = b2s[j];
#pragma unroll
        for (int k = 0; k < NHID; k++) acc = fmaf(h1[k], w2s[k * NHID + j], acc);
        float g = 0.5f * acc * (1.0f + erff(acc * 0.70710678118654752f));
        d_H2T[j * TLEN + t] = g;
    }
}

// ---------------- w3 GEMM: Filt[c][t] = sum_j H2T[j][t]*w3[j][c] + b3[c] ----------------
#define GT 256
#define GC 64
#define HSTR 257
__global__ __launch_bounds__(256) void gemm_w3_kernel(const float* __restrict__ w3,
                                                      const float* __restrict__ b3) {
    extern __shared__ float gsm[];
    float* Hp = gsm;                    // [64][HSTR]
    float* Ws = gsm + NHID * HSTR;      // [64][GC]
    int tid = threadIdx.x;
    int t0 = blockIdx.x * GT;
    int c0 = blockIdx.y * GC;
    for (int idx = tid; idx < NHID * GT; idx += 256) {
        int j = idx >> 8, t = idx & 255;
        Hp[j * HSTR + t] = d_H2T[j * TLEN + t0 + t];
    }
    for (int idx = tid; idx < NHID * GC; idx += 256) {
        int j = idx >> 6, c = idx & 63;
        Ws[idx] = w3[j * (NCIN * NCOUT) + c0 + c];
    }
    __syncthreads();
    int cg = tid & 15;
    int rg = tid >> 4;
    float4 bb = *(const float4*)&b3[c0 + cg * 4];
    float acc[16][4];
#pragma unroll
    for (int rr = 0; rr < 16; rr++) {
        acc[rr][0] = bb.x; acc[rr][1] = bb.y; acc[rr][2] = bb.z; acc[rr][3] = bb.w;
    }
#pragma unroll 4
    for (int j = 0; j < NHID; j++) {
        float4 w = *(const float4*)&Ws[j * GC + cg * 4];
        float h[16];
#pragma unroll
        for (int rr = 0; rr < 16; rr++) h[rr] = Hp[j * HSTR + rg + rr * 16];
#pragma unroll
        for (int rr = 0; rr < 16; rr++) {
            acc[rr][0] = fmaf(h[rr], w.x, acc[rr][0]);
            acc[rr][1] = fmaf(h[rr], w.y, acc[rr][1]);
            acc[rr][2] = fmaf(h[rr], w.z, acc[rr][2]);
            acc[rr][3] = fmaf(h[rr], w.w, acc[rr][3]);
        }
    }
    __syncthreads();
#pragma unroll
    for (int rr = 0; rr < 16; rr++) {
        int r = rg + rr * 16;
#pragma unroll
        for (int cc = 0; cc < 4; cc++) Hp[(cg * 4 + cc) * HSTR + r] = acc[rr][cc];
    }
    __syncthreads();
    for (int idx = tid; idx < GC * GT; idx += 256) {
        int c = idx >> 8, t = idx & 255;
        d_Filt[(size_t)(c0 + c) * TLEN + t0 + t] = Hp[c * HSTR + t];
    }
}

// ---------------- forward rfft kernels (device symbols referenced in DEVICE code) ----------------
__global__ __launch_bounds__(512) void rfft_x_kernel(const float* __restrict__ x) {
    extern __shared__ float2 sm[];
    int row = blockIdx.x;
    rfft_row(x + (size_t)row * TLEN, d_Xf + (size_t)row * NF, sm, sm + 4096, threadIdx.x);
}

__global__ __launch_bounds__(512) void rfft_filt_kernel() {
    extern __shared__ float2 sm[];
    int row = blockIdx.x;
    rfft_row(d_Filt + (size_t)row * TLEN, d_Ff + (size_t)row * NF, sm, sm + 4096, threadIdx.x);
}

// ---------------- frequency contraction ----------------
__global__ void contract_kernel() {
    __shared__ float2 Xs[4 * 256];
    __shared__ float2 Fs[4 * 1024];
    int tid = threadIdx.x;
    int f0 = blockIdx.x * 4;
    for (int idx = tid; idx < 1024; idx += 256) {
        int row = idx >> 2, fo = idx & 3;
        int f = f0 + fo;
        Xs[fo * 256 + row] = (f < NF) ? d_Xf[(size_t)row * NF + f] : make_float2(0.f, 0.f);
    }
    for (int idx = tid; idx < 4096; idx += 256) {
        int oi = idx >> 2, fo = idx & 3;
        int f = f0 + fo;
        int o = oi >> 5, i = oi & 31;
        Fs[fo * 1024 + i * 32 + o] = (f < NF) ? d_Ff[(size_t)oi * NF + f] : make_float2(0.f, 0.f);
    }
    __syncthreads();
    int b = tid >> 5, o = tid & 31;
    float2 res[4];
#pragma unroll
    for (int fo = 0; fo < 4; fo++) {
        float2 acc = make_float2(0.f, 0.f);
        const float2* Xp = Xs + fo * 256 + b * 32;
        const float2* Fp = Fs + fo * 1024 + o;
#pragma unroll 8
        for (int i = 0; i < 32; i++) {
            float2 xv = Xp[i];
            float2 fv = Fp[i * 32];
            acc.x = fmaf(xv.x, fv.x, acc.x);
            acc.x = fmaf(-xv.y, fv.y, acc.x);
            acc.y = fmaf(xv.x, fv.y, acc.y);
            acc.y = fmaf(xv.y, fv.x, acc.y);
        }
        res[fo] = acc;
    }
    __syncthreads();
#pragma unroll
    for (int fo = 0; fo < 4; fo++) Xs[fo * 256 + tid] = res[fo];
    __syncthreads();
    for (int idx = tid; idx < 1024; idx += 256) {
        int row = idx >> 2, fo = idx & 3;
        int f = f0 + fo;
        if (f < NF) d_Gf[(size_t)row * NF + f] = Xs[fo * 256 + row];
    }
}

// ---------------- inverse rfft + bias ----------------
__global__ __launch_bounds__(512) void irfft_kernel(const float* __restrict__ bias,
                                                    float* __restrict__ out) {
    extern __shared__ float2 sm[];
    float2* A = sm;
    float2* Bp = sm + 4096;
    int tid = threadIdx.x;
    int row = blockIdx.x;  // b*32+o
    const float2* G = d_Gf + (size_t)row * NF;
    for (int k = tid; k < MH; k += 512) {
        float2 Xk = G[k];
        float2 Xm = G[MH - k];
        float2 E = make_float2(0.5f * (Xk.x + Xm.x), 0.5f * (Xk.y - Xm.y));
        float2 D = make_float2(0.5f * (Xk.x - Xm.x), 0.5f * (Xk.y + Xm.y));
        float2 Wc = d_TW8[k];
        float2 Winv = make_float2(Wc.x, -Wc.y);
        float2 O = cmulf(Winv, D);
        A[k] = make_float2(E.x - O.y, -(E.y + O.x));  // conj(E + i*O)
    }
    __syncthreads();
    fft4096(A, A, Bp, tid);
    float bo = bias[row & 31];
    float2* orow = (float2*)(out + (size_t)row * TLEN);
    const float inv = 1.0f / (float)MH;
    for (int k = tid; k < MH; k += 512) {
        float2 z = A[k];
        orow[k] = make_float2(fmaf(z.x, inv, bo), fmaf(-z.y, inv, bo));
    }
}

// ---------------- launch ----------------
extern "C" void kernel_launch(void* const* d_in, const int* in_sizes, int n_in,
                              void* d_out, int out_size) {
    const float* x    = (const float*)d_in[0];
    const float* w1   = (const float*)d_in[1];
    const float* b1   = (const float*)d_in[2];
    const float* w2   = (const float*)d_in[3];
    const float* b2   = (const float*)d_in[4];
    const float* w3   = (const float*)d_in[5];
    const float* b3   = (const float*)d_in[6];
    const float* bias = (const float*)d_in[7];
    float* out = (float*)d_out;

    size_t gemm_smem = (NHID * HSTR + NHID * GC) * sizeof(float);
    cudaFuncSetAttribute(gemm_w3_kernel, cudaFuncAttributeMaxDynamicSharedMemorySize, (int)gemm_smem);
    cudaFuncSetAttribute(rfft_x_kernel, cudaFuncAttributeMaxDynamicSharedMemorySize, (int)FFT_SMEM);
    cudaFuncSetAttribute(rfft_filt_kernel, cudaFuncAttributeMaxDynamicSharedMemorySize, (int)FFT_SMEM);
    cudaFuncSetAttribute(irfft_kernel, cudaFuncAttributeMaxDynamicSharedMemorySize, (int)FFT_SMEM);

    init_tw_kernel<<<16, 512>>>();
    mlp_kernel<<<TLEN / 128, 128>>>(w1, b1, w2, b2);
    gemm_w3_kernel<<<dim3(TLEN / GT, (NCIN * NCOUT) / GC), 256, gemm_smem>>>(w3, b3);
    rfft_x_kernel<<<NB * NCIN, 512, FFT_SMEM>>>(x);
    rfft_filt_kernel<<<NCOUT * NCIN, 512, FFT_SMEM>>>();
    contract_kernel<<<(NF + 3) / 4, 256>>>();
    irfft_kernel<<<NB * NCOUT, 512, FFT_SMEM>>>(bias, out);
}

// round 5
// speedup vs baseline: 2.2041x; 1.1340x over previous
#include <cuda_runtime.h>

#define TLEN 8192
#define MH   4096
#define NF   4097
#define NHID 64
#define NCIN 32
#define NCOUT 32
#define NB   8
#define NCOL (NCIN * NCOUT)

// ---------------- device global scratch (allocation-free) ----------------
__device__ float2 d_TW8[TLEN];                 // e^{-2*pi*i*k/8192}
__device__ float  d_H2T[NHID * TLEN];          // MLP hidden, transposed [j][t]
__device__ float2 d_Hf[NHID * NF];             // rfft of hidden rows
__device__ float2 d_Xf[(NB * NCIN) * NF];      // rfft(x) rows
__device__ float2 d_Ff[NCOL * NF];             // filter spectra [c][f]
__device__ float2 d_Gf[(NB * NCOUT) * NF];     // contracted spectrum rows

__device__ __forceinline__ float2 cmulf(float2 a, float2 b) {
    return make_float2(fmaf(a.x, b.x, -a.y * b.y), fmaf(a.x, b.y, a.y * b.x));
}
__device__ __forceinline__ float2 cadd(float2 a, float2 b) { return make_float2(a.x + b.x, a.y + b.y); }
__device__ __forceinline__ float2 csub(float2 a, float2 b) { return make_float2(a.x - b.x, a.y - b.y); }
__device__ __forceinline__ float2 mulnegi(float2 a) { return make_float2(a.y, -a.x); }

#define PADIDX(a) ((a) + ((a) >> 3))

// ---------------- twiddle init ----------------
__global__ void init_tw_kernel() {
    int k = blockIdx.x * blockDim.x + threadIdx.x;
    if (k < TLEN) {
        double a = -2.0 * 3.14159265358979323846 * (double)k / (double)TLEN;
        d_TW8[k] = make_float2((float)cos(a), (float)sin(a));
    }
}

// ---------------- 8-point DFT in registers ----------------
__device__ __forceinline__ void fft8(const float2 c[8], float2 d[8]) {
    const float S = 0.70710678118654752440f;
    float2 a0 = cadd(c[0], c[4]), a1 = cadd(c[1], c[5]);
    float2 a2 = cadd(c[2], c[6]), a3 = cadd(c[3], c[7]);
    float2 b0 = csub(c[0], c[4]);
    float2 t1 = csub(c[1], c[5]);
    float2 b1 = make_float2(S * (t1.x + t1.y), S * (t1.y - t1.x));
    float2 t2 = csub(c[2], c[6]);
    float2 b2 = mulnegi(t2);
    float2 t3 = csub(c[3], c[7]);
    float2 b3 = make_float2(S * (t3.y - t3.x), -S * (t3.x + t3.y));
    float2 p0 = cadd(a0, a2), q0 = csub(a0, a2);
    float2 p1 = cadd(a1, a3), q1 = mulnegi(csub(a1, a3));
    d[0] = cadd(p0, p1); d[4] = csub(p0, p1);
    d[2] = cadd(q0, q1); d[6] = csub(q0, q1);
    float2 r0 = cadd(b0, b2), s0 = csub(b0, b2);
    float2 r1 = cadd(b1, b3), s1 = mulnegi(csub(b1, b3));
    d[1] = cadd(r0, r1); d[5] = csub(r0, r1);
    d[3] = cadd(s0, s1); d[7] = csub(s0, s1);
}

// ---------------- one radix-8 Stockham DIF stage ----------------
template <int L, int M, int SP, int DP>
__device__ __forceinline__ void stage8(const float2* __restrict__ src,
                                       float2* __restrict__ dst, int tid) {
    int j = tid / M;
    int k = tid - j * M;
    float2 c[8], d[8];
#pragma unroll
    for (int i = 0; i < 8; i++) {
        int a = tid + i * 512;
        c[i] = src[SP ? PADIDX(a) : a];
    }
    fft8(c, d);
    if (L > 1) {
        int tstep = j * (1024 / L);
        float2 w = d_TW8[tstep];
        float2 wt = w;
        d[1] = cmulf(d[1], w);
#pragma unroll
        for (int t = 2; t < 8; t++) {
            wt = cmulf(wt, w);
            d[t] = cmulf(d[t], wt);
        }
    }
    int base = k + M * 8 * j;
#pragma unroll
    for (int t = 0; t < 8; t++) {
        int a = base + M * t;
        dst[DP ? PADIDX(a) : a] = d[t];
    }
}

__device__ void fft4096(const float2* __restrict__ src, float2* A, float2* Bp, int tid) {
    stage8<512, 1, 0, 1>(src, Bp, tid);
    __syncthreads();
    stage8<64, 8, 1, 0>(Bp, A, tid);
    __syncthreads();
    stage8<8, 64, 0, 1>(A, Bp, tid);
    __syncthreads();
    stage8<1, 512, 1, 0>(Bp, A, tid);
    __syncthreads();
}

__device__ void rfft_post(const float2* A, float2* out, int tid) {
    for (int k = tid; k <= MH / 2; k += 512) {
        float2 Zk = A[k];
        float2 Zm = A[(MH - k) & (MH - 1)];
        float2 E = make_float2(0.5f * (Zk.x + Zm.x), 0.5f * (Zk.y - Zm.y));
        float2 O = make_float2(0.5f * (Zk.y + Zm.y), 0.5f * (Zm.x - Zk.x));
        float2 WO = cmulf(d_TW8[k], O);
        out[k]      = make_float2(E.x + WO.x, E.y + WO.y);
        out[MH - k] = make_float2(E.x - WO.x, -(E.y - WO.y));
    }
}

__device__ void rfft_row(const float* __restrict__ src_row, float2* __restrict__ dst_row,
                         float2* A, float2* Bp, int tid) {
    fft4096((const float2*)src_row, A, Bp, tid);
    rfft_post(A, dst_row, tid);
}

#define FFT_SMEM ((4096 + 4608) * sizeof(float2))

// ---------------- MLP hidden ----------------
__global__ void mlp_kernel(const float* __restrict__ w1, const float* __restrict__ b1,
                           const float* __restrict__ w2, const float* __restrict__ b2) {
    __shared__ float w2s[NHID * NHID];
    __shared__ float w1s[NHID], b1s[NHID], b2s[NHID];
    int tid = threadIdx.x;
    for (int i = tid; i < NHID * NHID; i += blockDim.x) w2s[i] = w2[i];
    if (tid < NHID) { w1s[tid] = w1[tid]; b1s[tid] = b1[tid]; b2s[tid] = b2[tid]; }
    __syncthreads();
    int t = blockIdx.x * blockDim.x + tid;
    float pos = (float)t / 8191.0f;
    float h1[NHID];
#pragma unroll
    for (int k = 0; k < NHID; k++) {
        float v = fmaf(pos, w1s[k], b1s[k]);
        h1[k] = 0.5f * v * (1.0f + erff(v * 0.70710678118654752f));
    }
    for (int j = 0; j < NHID; j++) {
        float acc = b2s[j];
#pragma unroll
        for (int k = 0; k < NHID; k++) acc = fmaf(h1[k], w2s[k * NHID + j], acc);
        float g = 0.5f * acc * (1.0f + erff(acc * 0.70710678118654752f));
        d_H2T[j * TLEN + t] = g;
    }
}

// ---------------- forward rfft kernels ----------------
__global__ __launch_bounds__(512) void rfft_x_kernel(const float* __restrict__ x) {
    extern __shared__ float2 sm[];
    int row = blockIdx.x;
    rfft_row(x + (size_t)row * TLEN, d_Xf + (size_t)row * NF, sm, sm + 4096, threadIdx.x);
}

__global__ __launch_bounds__(512) void rfft_h_kernel() {
    extern __shared__ float2 sm[];
    int row = blockIdx.x;  // j = 0..63
    rfft_row(d_H2T + (size_t)row * TLEN, d_Hf + (size_t)row * NF, sm, sm + 4096, threadIdx.x);
}

// ---------------- frequency-domain w3 GEMM ----------------
// Ff[c,f] = sum_j w3[j,c] * Hf[j,f]  (+ 8192*b3[c] at f==0)
#define FB 128
#define CB 64
__global__ __launch_bounds__(256) void gemm_freq_kernel(const float* __restrict__ w3,
                                                        const float* __restrict__ b3) {
    extern __shared__ float gfs[];
    float2* Hs = (float2*)gfs;              // [64][FB]  64KB
    float*  Ws = gfs + 2 * NHID * FB;       // [64][CB]  16KB
    int tid = threadIdx.x;
    int f0 = blockIdx.x * FB;
    int c0 = blockIdx.y * CB;
    for (int idx = tid; idx < NHID * FB; idx += 256) {
        int j = idx >> 7, f = idx & (FB - 1);
        Hs[j * FB + f] = (f0 + f < NF) ? d_Hf[(size_t)j * NF + f0 + f]
                                       : make_float2(0.f, 0.f);
    }
    for (int idx = tid; idx < NHID * CB; idx += 256) {
        int j = idx >> 6, c = idx & (CB - 1);
        Ws[idx] = w3[j * NCOL + c0 + c];
    }
    __syncthreads();
    int cq = tid & 15;   // 16 groups of 4 cols
    int fq = tid >> 4;   // 16 groups of 8 freqs
    float2 acc[4][8];
#pragma unroll
    for (int a = 0; a < 4; a++)
#pragma unroll
        for (int b = 0; b < 8; b++) acc[a][b] = make_float2(0.f, 0.f);
#pragma unroll 2
    for (int j = 0; j < NHID; j++) {
        float4 w = *(const float4*)&Ws[j * CB + cq * 4];
        float2 h[8];
#pragma unroll
        for (int b = 0; b < 8; b++) h[b] = Hs[j * FB + fq * 8 + b];
        float wv[4] = {w.x, w.y, w.z, w.w};
#pragma unroll
        for (int a = 0; a < 4; a++)
#pragma unroll
            for (int b = 0; b < 8; b++) {
                acc[a][b].x = fmaf(wv[a], h[b].x, acc[a][b].x);
                acc[a][b].y = fmaf(wv[a], h[b].y, acc[a][b].y);
            }
    }
#pragma unroll
    for (int a = 0; a < 4; a++) {
        int c = c0 + cq * 4 + a;
        float bv = 8192.0f * b3[c];
#pragma unroll
        for (int b = 0; b < 8; b++) {
            int f = f0 + fq * 8 + b;
            if (f < NF) {
                float2 v = acc[a][b];
                if (f == 0) v.x += bv;
                d_Ff[(size_t)c * NF + f] = v;
            }
        }
    }
}

// ---------------- frequency contraction ----------------
__global__ void contract_kernel() {
    __shared__ float2 Xs[4 * 256];
    __shared__ float2 Fs[4 * 1024];
    int tid = threadIdx.x;
    int f0 = blockIdx.x * 4;
    for (int idx = tid; idx < 1024; idx += 256) {
        int row = idx >> 2, fo = idx & 3;
        int f = f0 + fo;
        Xs[fo * 256 + row] = (f < NF) ? d_Xf[(size_t)row * NF + f] : make_float2(0.f, 0.f);
    }
    for (int idx = tid; idx < 4096; idx += 256) {
        int oi = idx >> 2, fo = idx & 3;
        int f = f0 + fo;
        int o = oi >> 5, i = oi & 31;
        Fs[fo * 1024 + i * 32 + o] = (f < NF) ? d_Ff[(size_t)oi * NF + f] : make_float2(0.f, 0.f);
    }
    __syncthreads();
    int b = tid >> 5, o = tid & 31;
    float2 res[4];
#pragma unroll
    for (int fo = 0; fo < 4; fo++) {
        float2 acc = make_float2(0.f, 0.f);
        const float2* Xp = Xs + fo * 256 + b * 32;
        const float2* Fp = Fs + fo * 1024 + o;
#pragma unroll 8
        for (int i = 0; i < 32; i++) {
            float2 xv = Xp[i];
            float2 fv = Fp[i * 32];
            acc.x = fmaf(xv.x, fv.x, acc.x);
            acc.x = fmaf(-xv.y, fv.y, acc.x);
            acc.y = fmaf(xv.x, fv.y, acc.y);
            acc.y = fmaf(xv.y, fv.x, acc.y);
        }
        res[fo] = acc;
    }
    __syncthreads();
#pragma unroll
    for (int fo = 0; fo < 4; fo++) Xs[fo * 256 + tid] = res[fo];
    __syncthreads();
    for (int idx = tid; idx < 1024; idx += 256) {
        int row = idx >> 2, fo = idx & 3;
        int f = f0 + fo;
        if (f < NF) d_Gf[(size_t)row * NF + f] = Xs[fo * 256 + row];
    }
}

// ---------------- inverse rfft + bias ----------------
__global__ __launch_bounds__(512) void irfft_kernel(const float* __restrict__ bias,
                                                    float* __restrict__ out) {
    extern __shared__ float2 sm[];
    float2* A = sm;
    float2* Bp = sm + 4096;
    int tid = threadIdx.x;
    int row = blockIdx.x;  // b*32+o
    const float2* G = d_Gf + (size_t)row * NF;
    for (int k = tid; k < MH; k += 512) {
        float2 Xk = G[k];
        float2 Xm = G[MH - k];
        float2 E = make_float2(0.5f * (Xk.x + Xm.x), 0.5f * (Xk.y - Xm.y));
        float2 D = make_float2(0.5f * (Xk.x - Xm.x), 0.5f * (Xk.y + Xm.y));
        float2 Wc = d_TW8[k];
        float2 Winv = make_float2(Wc.x, -Wc.y);
        float2 O = cmulf(Winv, D);
        A[k] = make_float2(E.x - O.y, -(E.y + O.x));
    }
    __syncthreads();
    fft4096(A, A, Bp, tid);
    float bo = bias[row & 31];
    float2* orow = (float2*)(out + (size_t)row * TLEN);
    const float inv = 1.0f / (float)MH;
    for (int k = tid; k < MH; k += 512) {
        float2 z = A[k];
        orow[k] = make_float2(fmaf(z.x, inv, bo), fmaf(-z.y, inv, bo));
    }
}

// ---------------- launch ----------------
extern "C" void kernel_launch(void* const* d_in, const int* in_sizes, int n_in,
                              void* d_out, int out_size) {
    const float* x    = (const float*)d_in[0];
    const float* w1   = (const float*)d_in[1];
    const float* b1   = (const float*)d_in[2];
    const float* w2   = (const float*)d_in[3];
    const float* b2   = (const float*)d_in[4];
    const float* w3   = (const float*)d_in[5];
    const float* b3   = (const float*)d_in[6];
    const float* bias = (const float*)d_in[7];
    float* out = (float*)d_out;

    size_t gf_smem = (2 * NHID * FB + NHID * CB) * sizeof(float);
    cudaFuncSetAttribute(gemm_freq_kernel, cudaFuncAttributeMaxDynamicSharedMemorySize, (int)gf_smem);
    cudaFuncSetAttribute(rfft_x_kernel, cudaFuncAttributeMaxDynamicSharedMemorySize, (int)FFT_SMEM);
    cudaFuncSetAttribute(rfft_h_kernel, cudaFuncAttributeMaxDynamicSharedMemorySize, (int)FFT_SMEM);
    cudaFuncSetAttribute(irfft_kernel, cudaFuncAttributeMaxDynamicSharedMemorySize, (int)FFT_SMEM);

    init_tw_kernel<<<16, 512>>>();
    mlp_kernel<<<TLEN / 128, 128>>>(w1, b1, w2, b2);
    rfft_h_kernel<<<NHID, 512, FFT_SMEM>>>();
    gemm_freq_kernel<<<dim3((NF + FB - 1) / FB, NCOL / CB), 256, gf_smem>>>(w3, b3);
    rfft_x_kernel<<<NB * NCIN, 512, FFT_SMEM>>>(x);
    contract_kernel<<<(NF + 3) / 4, 256>>>();
    irfft_kernel<<<NB * NCOUT, 512, FFT_SMEM>>>(bias, out);
}

// round 10
// speedup vs baseline: 2.5952x; 1.1774x over previous
#include <cuda_runtime.h>
#include <cuda_bf16.h>
#include <cstdint>

#define TLEN 8192
#define MH   4096
#define NF   4097
#define NHID 64
#define NCIN 32
#define NCOUT 32
#define NB   8
#define NCOL (NCIN * NCOUT)
#define QPAD (65 * 128)

// ---------------- device global scratch (allocation-free) ----------------
__device__ float2 d_TW8[TLEN];                 // e^{-2*pi*i*k/8192}
__device__ float  d_H2T[NHID * TLEN];          // MLP hidden, transposed [j][t]
__device__ float2 d_Hf[NHID * NF];             // rfft of hidden rows
__device__ float2 d_Xf[(NB * NCIN) * NF];      // rfft(x) rows
__device__ float2 d_Ff[NCOL * NF];             // filter spectra [c][f]
__device__ float2 d_Gf[(NB * NCOUT) * NF];     // contracted spectrum rows
__device__ __nv_bfloat16 d_w3hi[NCOL * NHID];  // w3 transposed [c][j], hi part
__device__ __nv_bfloat16 d_w3lo[NCOL * NHID];  // lo part
__device__ __nv_bfloat16 d_Bhi[QPAD * NHID];   // Hr transposed [q][j], hi
__device__ __nv_bfloat16 d_Blo[QPAD * NHID];   // lo

__device__ __forceinline__ float2 cmulf(float2 a, float2 b) {
    return make_float2(fmaf(a.x, b.x, -a.y * b.y), fmaf(a.x, b.y, a.y * b.x));
}
__device__ __forceinline__ float2 cadd(float2 a, float2 b) { return make_float2(a.x + b.x, a.y + b.y); }
__device__ __forceinline__ float2 csub(float2 a, float2 b) { return make_float2(a.x - b.x, a.y - b.y); }
__device__ __forceinline__ float2 mulnegi(float2 a) { return make_float2(a.y, -a.x); }

#define PADIDX(a) ((a) + ((a) >> 3))

// ---------------- twiddle init ----------------
__global__ void init_tw_kernel() {
    int k = blockIdx.x * blockDim.x + threadIdx.x;
    if (k < TLEN) {
        double a = -2.0 * 3.14159265358979323846 * (double)k / (double)TLEN;
        d_TW8[k] = make_float2((float)cos(a), (float)sin(a));
    }
}

// ---------------- 8-point DFT in registers ----------------
__device__ __forceinline__ void fft8(const float2 c[8], float2 d[8]) {
    const float S = 0.70710678118654752440f;
    float2 a0 = cadd(c[0], c[4]), a1 = cadd(c[1], c[5]);
    float2 a2 = cadd(c[2], c[6]), a3 = cadd(c[3], c[7]);
    float2 b0 = csub(c[0], c[4]);
    float2 t1 = csub(c[1], c[5]);
    float2 b1 = make_float2(S * (t1.x + t1.y), S * (t1.y - t1.x));
    float2 t2 = csub(c[2], c[6]);
    float2 b2 = mulnegi(t2);
    float2 t3 = csub(c[3], c[7]);
    float2 b3 = make_float2(S * (t3.y - t3.x), -S * (t3.x + t3.y));
    float2 p0 = cadd(a0, a2), q0 = csub(a0, a2);
    float2 p1 = cadd(a1, a3), q1 = mulnegi(csub(a1, a3));
    d[0] = cadd(p0, p1); d[4] = csub(p0, p1);
    d[2] = cadd(q0, q1); d[6] = csub(q0, q1);
    float2 r0 = cadd(b0, b2), s0 = csub(b0, b2);
    float2 r1 = cadd(b1, b3), s1 = mulnegi(csub(b1, b3));
    d[1] = cadd(r0, r1); d[5] = csub(r0, r1);
    d[3] = cadd(s0, s1); d[7] = csub(s0, s1);
}

template <int L, int M, int SP, int DP>
__device__ __forceinline__ void stage8(const float2* __restrict__ src,
                                       float2* __restrict__ dst, int tid) {
    int j = tid / M;
    int k = tid - j * M;
    float2 c[8], d[8];
#pragma unroll
    for (int i = 0; i < 8; i++) {
        int a = tid + i * 512;
        c[i] = src[SP ? PADIDX(a) : a];
    }
    fft8(c, d);
    if (L > 1) {
        int tstep = j * (1024 / L);
        float2 w = d_TW8[tstep];
        float2 wt = w;
        d[1] = cmulf(d[1], w);
#pragma unroll
        for (int t = 2; t < 8; t++) {
            wt = cmulf(wt, w);
            d[t] = cmulf(d[t], wt);
        }
    }
    int base = k + M * 8 * j;
#pragma unroll
    for (int t = 0; t < 8; t++) {
        int a = base + M * t;
        dst[DP ? PADIDX(a) : a] = d[t];
    }
}

__device__ void fft4096(const float2* __restrict__ src, float2* A, float2* Bp, int tid) {
    stage8<512, 1, 0, 1>(src, Bp, tid);
    __syncthreads();
    stage8<64, 8, 1, 0>(Bp, A, tid);
    __syncthreads();
    stage8<8, 64, 0, 1>(A, Bp, tid);
    __syncthreads();
    stage8<1, 512, 1, 0>(Bp, A, tid);
    __syncthreads();
}

__device__ void rfft_post(const float2* A, float2* out, int tid) {
    for (int k = tid; k <= MH / 2; k += 512) {
        float2 Zk = A[k];
        float2 Zm = A[(MH - k) & (MH - 1)];
        float2 E = make_float2(0.5f * (Zk.x + Zm.x), 0.5f * (Zk.y - Zm.y));
        float2 O = make_float2(0.5f * (Zk.y + Zm.y), 0.5f * (Zm.x - Zk.x));
        float2 WO = cmulf(d_TW8[k], O);
        out[k]      = make_float2(E.x + WO.x, E.y + WO.y);
        out[MH - k] = make_float2(E.x - WO.x, -(E.y - WO.y));
    }
}

__device__ void rfft_row(const float* __restrict__ src_row, float2* __restrict__ dst_row,
                         float2* A, float2* Bp, int tid) {
    fft4096((const float2*)src_row, A, Bp, tid);
    rfft_post(A, dst_row, tid);
}

#define FFT_SMEM ((4096 + 4608) * sizeof(float2))

// ---------------- MLP hidden ----------------
__global__ void mlp_kernel(const float* __restrict__ w1, const float* __restrict__ b1,
                           const float* __restrict__ w2, const float* __restrict__ b2) {
    __shared__ float w2s[NHID * NHID];
    __shared__ float w1s[NHID], b1s[NHID], b2s[NHID];
    int tid = threadIdx.x;
    for (int i = tid; i < NHID * NHID; i += blockDim.x) w2s[i] = w2[i];
    if (tid < NHID) { w1s[tid] = w1[tid]; b1s[tid] = b1[tid]; b2s[tid] = b2[tid]; }
    __syncthreads();
    int t = blockIdx.x * blockDim.x + tid;
    float pos = (float)t / 8191.0f;
    float h1[NHID];
#pragma unroll
    for (int k = 0; k < NHID; k++) {
        float v = fmaf(pos, w1s[k], b1s[k]);
        h1[k] = 0.5f * v * (1.0f + erff(v * 0.70710678118654752f));
    }
    for (int j = 0; j < NHID; j++) {
        float acc = b2s[j];
#pragma unroll
        for (int k = 0; k < NHID; k++) acc = fmaf(h1[k], w2s[k * NHID + j], acc);
        float g = 0.5f * acc * (1.0f + erff(acc * 0.70710678118654752f));
        d_H2T[j * TLEN + t] = g;
    }
}

// ---------------- forward rfft kernels ----------------
__global__ __launch_bounds__(512) void rfft_x_kernel(const float* __restrict__ x) {
    extern __shared__ float2 sm[];
    int row = blockIdx.x;
    rfft_row(x + (size_t)row * TLEN, d_Xf + (size_t)row * NF, sm, sm + 4096, threadIdx.x);
}

__global__ __launch_bounds__(512) void rfft_h_kernel() {
    extern __shared__ float2 sm[];
    int row = blockIdx.x;
    rfft_row(d_H2T + (size_t)row * TLEN, d_Hf + (size_t)row * NF, sm, sm + 4096, threadIdx.x);
}

// ---------------- prep: w3 transpose + bf16 hi/lo split ----------------
__global__ void prep_w3_kernel(const float* __restrict__ w3) {
    int idx = blockIdx.x * 256 + threadIdx.x;  // 65536
    int c = idx >> 6, j = idx & 63;
    float x = w3[j * NCOL + c];
    __nv_bfloat16 h = __float2bfloat16(x);
    d_w3hi[idx] = h;
    d_w3lo[idx] = __float2bfloat16(x - __bfloat162float(h));
}

// ---------------- prep: Hf -> [q][j] bf16 hi/lo (smem transpose) ----------------
__global__ void prep_B_kernel() {
    __shared__ float2 sf[64][65];
    int tid = threadIdx.x;
    int q0 = blockIdx.x * 128;
    int f0 = q0 >> 1;
    for (int idx = tid; idx < 64 * 64; idx += 256) {
        int j = idx >> 6, fi = idx & 63;
        int f = f0 + fi;
        sf[j][fi] = (f < NF) ? d_Hf[(size_t)j * NF + f] : make_float2(0.f, 0.f);
    }
    __syncthreads();
    for (int idx = tid; idx < 128 * 64; idx += 256) {
        int q = idx >> 6, j = idx & 63;
        float2 v = sf[j][q >> 1];
        float x = (q & 1) ? v.y : v.x;
        __nv_bfloat16 h = __float2bfloat16(x);
        int o = (q0 + q) * 64 + j;
        d_Bhi[o] = h;
        d_Blo[o] = __float2bfloat16(x - __bfloat162float(h));
    }
}

// ---------------- HMMA frequency GEMM (mma.sync, baseline PTX) ----------------
// C[c,q] = sum_j w3[j,c]*Hr[j,q], bf16 hi/lo 3-term split (hh + hl + lh).
// CTA tile 128x128, 8 warps (4 in M x 2 in N), warp tile 32x64.
#define ASTR 72   // smem row stride in bf16 (144B: conflict-free fragment loads)

__device__ __forceinline__ void mma16816(float c[4], const uint32_t a[4],
                                         uint32_t b0, uint32_t b1) {
    asm volatile(
        "mma.sync.aligned.m16n8k16.row.col.f32.bf16.bf16.f32 "
        "{%0,%1,%2,%3}, {%4,%5,%6,%7}, {%8,%9}, {%0,%1,%2,%3};"
        : "+f"(c[0]), "+f"(c[1]), "+f"(c[2]), "+f"(c[3])
        : "r"(a[0]), "r"(a[1]), "r"(a[2]), "r"(a[3]), "r"(b0), "r"(b1));
}

__global__ __launch_bounds__(256) void gemm_mma_kernel(const float* __restrict__ b3) {
    extern __shared__ __nv_bfloat16 ms[];
    __nv_bfloat16* Ah = ms;                    // [128][ASTR]
    __nv_bfloat16* Al = Ah + 128 * ASTR;
    __nv_bfloat16* Bh = Al + 128 * ASTR;
    __nv_bfloat16* Bl = Bh + 128 * ASTR;
    int tid = threadIdx.x;
    int q0 = blockIdx.x * 128;
    int c0 = blockIdx.y * 128;

    const uint4* w3h4 = (const uint4*)d_w3hi;
    const uint4* w3l4 = (const uint4*)d_w3lo;
    const uint4* bh4  = (const uint4*)d_Bhi;
    const uint4* bl4  = (const uint4*)d_Blo;
#pragma unroll
    for (int it = 0; it < 4; it++) {
        int idx = it * 256 + tid;          // 1024 uint4 per array
        int r = idx >> 3, u = idx & 7;
        *(uint4*)(Ah + r * ASTR + u * 8) = w3h4[(c0 + r) * 8 + u];
        *(uint4*)(Al + r * ASTR + u * 8) = w3l4[(c0 + r) * 8 + u];
        *(uint4*)(Bh + r * ASTR + u * 8) = bh4[(q0 + r) * 8 + u];
        *(uint4*)(Bl + r * ASTR + u * 8) = bl4[(q0 + r) * 8 + u];
    }
    __syncthreads();

    int wid = tid >> 5, l = tid & 31;
    int wm = (wid & 3) * 32;   // warp row base (c)
    int wn = (wid >> 2) * 64;  // warp col base (q)
    int lr = l >> 2;           // lane row 0..7
    int lc = (l & 3) * 2;      // lane col pair (bf16 units)

    float acc[2][8][4];
#pragma unroll
    for (int mi = 0; mi < 2; mi++)
#pragma unroll
        for (int ni = 0; ni < 8; ni++)
#pragma unroll
            for (int r = 0; r < 4; r++) acc[mi][ni][r] = 0.f;

    const __nv_bfloat16* Aterm[3] = {Ah, Ah, Al};
    const __nv_bfloat16* Bterm[3] = {Bh, Bl, Bh};
#pragma unroll
    for (int t = 0; t < 3; t++) {
        const __nv_bfloat16* A = Aterm[t];
        const __nv_bfloat16* B = Bterm[t];
#pragma unroll
        for (int k = 0; k < 4; k++) {
            int kb = k * 16;
            uint32_t af[2][4];
#pragma unroll
            for (int mi = 0; mi < 2; mi++) {
                int row = wm + mi * 16 + lr;
                af[mi][0] = *(const uint32_t*)(A + row * ASTR + kb + lc);
                af[mi][1] = *(const uint32_t*)(A + (row + 8) * ASTR + kb + lc);
                af[mi][2] = *(const uint32_t*)(A + row * ASTR + kb + 8 + lc);
                af[mi][3] = *(const uint32_t*)(A + (row + 8) * ASTR + kb + 8 + lc);
            }
#pragma unroll
            for (int ni = 0; ni < 8; ni++) {
                int nrow = wn + ni * 8 + lr;
                uint32_t b0 = *(const uint32_t*)(B + nrow * ASTR + kb + lc);
                uint32_t b1 = *(const uint32_t*)(B + nrow * ASTR + kb + 8 + lc);
                mma16816(acc[0][ni], af[0], b0, b1);
                mma16816(acc[1][ni], af[1], b0, b1);
            }
        }
    }

    // store: (c0,c1) = one float2 complex at [row][f], (c2,c3) at [row+8][f]
#pragma unroll
    for (int mi = 0; mi < 2; mi++) {
        int crow = c0 + wm + mi * 16 + lr;
        float bv0 = 8192.0f * b3[crow];
        float bv1 = 8192.0f * b3[crow + 8];
#pragma unroll
        for (int ni = 0; ni < 8; ni++) {
            int q = q0 + wn + ni * 8 + lc;
            int f = q >> 1;
            if (f < NF) {
                float2 v0 = make_float2(acc[mi][ni][0], acc[mi][ni][1]);
                float2 v1 = make_float2(acc[mi][ni][2], acc[mi][ni][3]);
                if (f == 0) { v0.x += bv0; v1.x += bv1; }
                d_Ff[(size_t)crow * NF + f] = v0;
                d_Ff[(size_t)(crow + 8) * NF + f] = v1;
            }
        }
    }
}

#define MMA_SMEM (4 * 128 * ASTR * sizeof(__nv_bfloat16))

// ---------------- frequency contraction ----------------
__global__ void contract_kernel() {
    __shared__ float2 Xs[4 * 256];
    __shared__ float2 Fs[4 * 1024];
    int tid = threadIdx.x;
    int f0 = blockIdx.x * 4;
    for (int idx = tid; idx < 1024; idx += 256) {
        int row = idx >> 2, fo = idx & 3;
        int f = f0 + fo;
        Xs[fo * 256 + row] = (f < NF) ? d_Xf[(size_t)row * NF + f] : make_float2(0.f, 0.f);
    }
    for (int idx = tid; idx < 4096; idx += 256) {
        int oi = idx >> 2, fo = idx & 3;
        int f = f0 + fo;
        int o = oi >> 5, i = oi & 31;
        Fs[fo * 1024 + i * 32 + o] = (f < NF) ? d_Ff[(size_t)oi * NF + f] : make_float2(0.f, 0.f);
    }
    __syncthreads();
    int b = tid >> 5, o = tid & 31;
    float2 res[4];
#pragma unroll
    for (int fo = 0; fo < 4; fo++) {
        float2 acc = make_float2(0.f, 0.f);
        const float2* Xp = Xs + fo * 256 + b * 32;
        const float2* Fp = Fs + fo * 1024 + o;
#pragma unroll 8
        for (int i = 0; i < 32; i++) {
            float2 xv = Xp[i];
            float2 fv = Fp[i * 32];
            acc.x = fmaf(xv.x, fv.x, acc.x);
            acc.x = fmaf(-xv.y, fv.y, acc.x);
            acc.y = fmaf(xv.x, fv.y, acc.y);
            acc.y = fmaf(xv.y, fv.x, acc.y);
        }
        res[fo] = acc;
    }
    __syncthreads();
#pragma unroll
    for (int fo = 0; fo < 4; fo++) Xs[fo * 256 + tid] = res[fo];
    __syncthreads();
    for (int idx = tid; idx < 1024; idx += 256) {
        int row = idx >> 2, fo = idx & 3;
        int f = f0 + fo;
        if (f < NF) d_Gf[(size_t)row * NF + f] = Xs[fo * 256 + row];
    }
}

// ---------------- inverse rfft + bias ----------------
__global__ __launch_bounds__(512) void irfft_kernel(const float* __restrict__ bias,
                                                    float* __restrict__ out) {
    extern __shared__ float2 sm[];
    float2* A = sm;
    float2* Bp = sm + 4096;
    int tid = threadIdx.x;
    int row = blockIdx.x;
    const float2* G = d_Gf + (size_t)row * NF;
    for (int k = tid; k < MH; k += 512) {
        float2 Xk = G[k];
        float2 Xm = G[MH - k];
        float2 E = make_float2(0.5f * (Xk.x + Xm.x), 0.5f * (Xk.y - Xm.y));
        float2 D = make_float2(0.5f * (Xk.x - Xm.x), 0.5f * (Xk.y + Xm.y));
        float2 Wc = d_TW8[k];
        float2 Winv = make_float2(Wc.x, -Wc.y);
        float2 O = cmulf(Winv, D);
        A[k] = make_float2(E.x - O.y, -(E.y + O.x));
    }
    __syncthreads();
    fft4096(A, A, Bp, tid);
    float bo = bias[row & 31];
    float2* orow = (float2*)(out + (size_t)row * TLEN);
    const float inv = 1.0f / (float)MH;
    for (int k = tid; k < MH; k += 512) {
        float2 z = A[k];
        orow[k] = make_float2(fmaf(z.x, inv, bo), fmaf(-z.y, inv, bo));
    }
}

// ---------------- launch ----------------
extern "C" void kernel_launch(void* const* d_in, const int* in_sizes, int n_in,
                              void* d_out, int out_size) {
    const float* x    = (const float*)d_in[0];
    const float* w1   = (const float*)d_in[1];
    const float* b1   = (const float*)d_in[2];
    const float* w2   = (const float*)d_in[3];
    const float* b2   = (const float*)d_in[4];
    const float* w3   = (const float*)d_in[5];
    const float* b3   = (const float*)d_in[6];
    const float* bias = (const float*)d_in[7];
    float* out = (float*)d_out;

    cudaFuncSetAttribute(rfft_x_kernel, cudaFuncAttributeMaxDynamicSharedMemorySize, (int)FFT_SMEM);
    cudaFuncSetAttribute(rfft_h_kernel, cudaFuncAttributeMaxDynamicSharedMemorySize, (int)FFT_SMEM);
    cudaFuncSetAttribute(irfft_kernel, cudaFuncAttributeMaxDynamicSharedMemorySize, (int)FFT_SMEM);
    cudaFuncSetAttribute(gemm_mma_kernel, cudaFuncAttributeMaxDynamicSharedMemorySize, (int)MMA_SMEM);

    init_tw_kernel<<<16, 512>>>();
    mlp_kernel<<<TLEN / 128, 128>>>(w1, b1, w2, b2);
    rfft_h_kernel<<<NHID, 512, FFT_SMEM>>>();
    prep_w3_kernel<<<NCOL * NHID / 256, 256>>>(w3);
    prep_B_kernel<<<QPAD / 128, 256>>>();
    gemm_mma_kernel<<<dim3(QPAD / 128, NCOL / 128), 256, MMA_SMEM>>>(b3);
    rfft_x_kernel<<<NB * NCIN, 512, FFT_SMEM>>>(x);
    contract_kernel<<<(NF + 3) / 4, 256>>>();
    irfft_kernel<<<NB * NCOUT, 512, FFT_SMEM>>>(bias, out);
}

// round 11
// speedup vs baseline: 2.7993x; 1.0786x over previous
#include <cuda_runtime.h>
#include <cuda_bf16.h>
#include <cstdint>

#define TLEN 8192
#define MH   4096
#define NF   4097
#define NHID 64
#define NCIN 32
#define NCOUT 32
#define NB   8
#define NCOL (NCIN * NCOUT)
#define QPAD (65 * 128)

// ---------------- device global scratch (allocation-free) ----------------
__device__ float2 d_TW8[TLEN];                 // e^{-2*pi*i*k/8192}
__device__ float  d_H2T[NHID * TLEN];          // MLP hidden, transposed [j][t]
__device__ float2 d_Hf[NHID * NF];             // rfft of hidden rows
__device__ float2 d_Xf[(NB * NCIN) * NF];      // rfft(x) rows
__device__ float2 d_Ff[NCOL * NF];             // filter spectra [c][f]
__device__ float2 d_Gf[(NB * NCOUT) * NF];     // contracted spectrum rows
__device__ __nv_bfloat16 d_w3hi[NCOL * NHID];  // w3 transposed [c][j], hi part
__device__ __nv_bfloat16 d_w3lo[NCOL * NHID];  // lo part
__device__ __nv_bfloat16 d_Bhi[QPAD * NHID];   // Hr transposed [q][j], hi
__device__ __nv_bfloat16 d_Blo[QPAD * NHID];   // lo

__device__ __forceinline__ float2 cmulf(float2 a, float2 b) {
    return make_float2(fmaf(a.x, b.x, -a.y * b.y), fmaf(a.x, b.y, a.y * b.x));
}
__device__ __forceinline__ float2 cadd(float2 a, float2 b) { return make_float2(a.x + b.x, a.y + b.y); }
__device__ __forceinline__ float2 csub(float2 a, float2 b) { return make_float2(a.x - b.x, a.y - b.y); }
__device__ __forceinline__ float2 mulnegi(float2 a) { return make_float2(a.y, -a.x); }

#define PADIDX(a) ((a) + ((a) >> 3))

// ---------------- twiddle init ----------------
__global__ void init_tw_kernel() {
    int k = blockIdx.x * blockDim.x + threadIdx.x;
    if (k < TLEN) {
        double a = -2.0 * 3.14159265358979323846 * (double)k / (double)TLEN;
        d_TW8[k] = make_float2((float)cos(a), (float)sin(a));
    }
}

// ---------------- 8-point DFT in registers ----------------
__device__ __forceinline__ void fft8(const float2 c[8], float2 d[8]) {
    const float S = 0.70710678118654752440f;
    float2 a0 = cadd(c[0], c[4]), a1 = cadd(c[1], c[5]);
    float2 a2 = cadd(c[2], c[6]), a3 = cadd(c[3], c[7]);
    float2 b0 = csub(c[0], c[4]);
    float2 t1 = csub(c[1], c[5]);
    float2 b1 = make_float2(S * (t1.x + t1.y), S * (t1.y - t1.x));
    float2 t2 = csub(c[2], c[6]);
    float2 b2 = mulnegi(t2);
    float2 t3 = csub(c[3], c[7]);
    float2 b3 = make_float2(S * (t3.y - t3.x), -S * (t3.x + t3.y));
    float2 p0 = cadd(a0, a2), q0 = csub(a0, a2);
    float2 p1 = cadd(a1, a3), q1 = mulnegi(csub(a1, a3));
    d[0] = cadd(p0, p1); d[4] = csub(p0, p1);
    d[2] = cadd(q0, q1); d[6] = csub(q0, q1);
    float2 r0 = cadd(b0, b2), s0 = csub(b0, b2);
    float2 r1 = cadd(b1, b3), s1 = mulnegi(csub(b1, b3));
    d[1] = cadd(r0, r1); d[5] = csub(r0, r1);
    d[3] = cadd(s0, s1); d[7] = csub(s0, s1);
}

template <int L, int M, int SP, int DP>
__device__ __forceinline__ void stage8(const float2* __restrict__ src,
                                       float2* __restrict__ dst, int tid) {
    int j = tid / M;
    int k = tid - j * M;
    float2 c[8], d[8];
#pragma unroll
    for (int i = 0; i < 8; i++) {
        int a = tid + i * 512;
        c[i] = src[SP ? PADIDX(a) : a];
    }
    fft8(c, d);
    if (L > 1) {
        int tstep = j * (1024 / L);
        float2 w = d_TW8[tstep];
        float2 wt = w;
        d[1] = cmulf(d[1], w);
#pragma unroll
        for (int t = 2; t < 8; t++) {
            wt = cmulf(wt, w);
            d[t] = cmulf(d[t], wt);
        }
    }
    int base = k + M * 8 * j;
#pragma unroll
    for (int t = 0; t < 8; t++) {
        int a = base + M * t;
        dst[DP ? PADIDX(a) : a] = d[t];
    }
}

__device__ void fft4096(const float2* __restrict__ src, float2* A, float2* Bp, int tid) {
    stage8<512, 1, 0, 1>(src, Bp, tid);
    __syncthreads();
    stage8<64, 8, 1, 0>(Bp, A, tid);
    __syncthreads();
    stage8<8, 64, 0, 1>(A, Bp, tid);
    __syncthreads();
    stage8<1, 512, 1, 0>(Bp, A, tid);
    __syncthreads();
}

__device__ void rfft_post(const float2* A, float2* out, int tid) {
    for (int k = tid; k <= MH / 2; k += 512) {
        float2 Zk = A[k];
        float2 Zm = A[(MH - k) & (MH - 1)];
        float2 E = make_float2(0.5f * (Zk.x + Zm.x), 0.5f * (Zk.y - Zm.y));
        float2 O = make_float2(0.5f * (Zk.y + Zm.y), 0.5f * (Zm.x - Zk.x));
        float2 WO = cmulf(d_TW8[k], O);
        out[k]      = make_float2(E.x + WO.x, E.y + WO.y);
        out[MH - k] = make_float2(E.x - WO.x, -(E.y - WO.y));
    }
}

__device__ void rfft_row(const float* __restrict__ src_row, float2* __restrict__ dst_row,
                         float2* A, float2* Bp, int tid) {
    fft4096((const float2*)src_row, A, Bp, tid);
    rfft_post(A, dst_row, tid);
}

#define FFT_SMEM ((4096 + 4608) * sizeof(float2))

// ---------------- MLP hidden ----------------
__global__ void mlp_kernel(const float* __restrict__ w1, const float* __restrict__ b1,
                           const float* __restrict__ w2, const float* __restrict__ b2) {
    __shared__ float w2s[NHID * NHID];
    __shared__ float w1s[NHID], b1s[NHID], b2s[NHID];
    int tid = threadIdx.x;
    for (int i = tid; i < NHID * NHID; i += blockDim.x) w2s[i] = w2[i];
    if (tid < NHID) { w1s[tid] = w1[tid]; b1s[tid] = b1[tid]; b2s[tid] = b2[tid]; }
    __syncthreads();
    int t = blockIdx.x * blockDim.x + tid;
    float pos = (float)t / 8191.0f;
    float h1[NHID];
#pragma unroll
    for (int k = 0; k < NHID; k++) {
        float v = fmaf(pos, w1s[k], b1s[k]);
        h1[k] = 0.5f * v * (1.0f + erff(v * 0.70710678118654752f));
    }
    for (int j = 0; j < NHID; j++) {
        float acc = b2s[j];
#pragma unroll
        for (int k = 0; k < NHID; k++) acc = fmaf(h1[k], w2s[k * NHID + j], acc);
        float g = 0.5f * acc * (1.0f + erff(acc * 0.70710678118654752f));
        d_H2T[j * TLEN + t] = g;
    }
}

// ---------------- forward rfft kernels ----------------
__global__ __launch_bounds__(512) void rfft_x_kernel(const float* __restrict__ x) {
    extern __shared__ float2 sm[];
    int row = blockIdx.x;
    rfft_row(x + (size_t)row * TLEN, d_Xf + (size_t)row * NF, sm, sm + 4096, threadIdx.x);
}

__global__ __launch_bounds__(512) void rfft_h_kernel() {
    extern __shared__ float2 sm[];
    int row = blockIdx.x;
    rfft_row(d_H2T + (size_t)row * TLEN, d_Hf + (size_t)row * NF, sm, sm + 4096, threadIdx.x);
}

// ---------------- prep: w3 transpose + bf16 hi/lo split (coalesced) ----------------
__global__ void prep_w3_kernel(const float* __restrict__ w3) {
    __shared__ float tile[64][65];
    int tid = threadIdx.x;
    int c0 = blockIdx.x * 64;
    for (int idx = tid; idx < 64 * 64; idx += 256) {
        int j = idx >> 6, cc = idx & 63;
        tile[j][cc] = w3[j * NCOL + c0 + cc];
    }
    __syncthreads();
    for (int idx = tid; idx < 64 * 64; idx += 256) {
        int cc = idx >> 6, j = idx & 63;
        float x = tile[j][cc];
        __nv_bfloat16 h = __float2bfloat16(x);
        int o = (c0 + cc) * 64 + j;
        d_w3hi[o] = h;
        d_w3lo[o] = __float2bfloat16(x - __bfloat162float(h));
    }
}

// ---------------- prep: Hf -> [q][j] bf16 hi/lo (smem transpose) ----------------
__global__ void prep_B_kernel() {
    __shared__ float2 sf[64][65];
    int tid = threadIdx.x;
    int q0 = blockIdx.x * 128;
    int f0 = q0 >> 1;
    for (int idx = tid; idx < 64 * 64; idx += 256) {
        int j = idx >> 6, fi = idx & 63;
        int f = f0 + fi;
        sf[j][fi] = (f < NF) ? d_Hf[(size_t)j * NF + f] : make_float2(0.f, 0.f);
    }
    __syncthreads();
    for (int idx = tid; idx < 128 * 64; idx += 256) {
        int q = idx >> 6, j = idx & 63;
        float2 v = sf[j][q >> 1];
        float x = (q & 1) ? v.y : v.x;
        __nv_bfloat16 h = __float2bfloat16(x);
        int o = (q0 + q) * 64 + j;
        d_Bhi[o] = h;
        d_Blo[o] = __float2bfloat16(x - __bfloat162float(h));
    }
}

// ---------------- HMMA frequency GEMM (mma.sync, baseline PTX) ----------------
#define ASTR 72

__device__ __forceinline__ void mma16816(float c[4], const uint32_t a[4],
                                         uint32_t b0, uint32_t b1) {
    asm volatile(
        "mma.sync.aligned.m16n8k16.row.col.f32.bf16.bf16.f32 "
        "{%0,%1,%2,%3}, {%4,%5,%6,%7}, {%8,%9}, {%0,%1,%2,%3};"
        : "+f"(c[0]), "+f"(c[1]), "+f"(c[2]), "+f"(c[3])
        : "r"(a[0]), "r"(a[1]), "r"(a[2]), "r"(a[3]), "r"(b0), "r"(b1));
}

__global__ __launch_bounds__(256) void gemm_mma_kernel(const float* __restrict__ b3) {
    extern __shared__ __nv_bfloat16 ms[];
    __nv_bfloat16* Ah = ms;                    // [128][ASTR]
    __nv_bfloat16* Al = Ah + 128 * ASTR;
    __nv_bfloat16* Bh = Al + 128 * ASTR;
    __nv_bfloat16* Bl = Bh + 128 * ASTR;
    int tid = threadIdx.x;
    int q0 = blockIdx.x * 128;
    int c0 = blockIdx.y * 128;

    const uint4* w3h4 = (const uint4*)d_w3hi;
    const uint4* w3l4 = (const uint4*)d_w3lo;
    const uint4* bh4  = (const uint4*)d_Bhi;
    const uint4* bl4  = (const uint4*)d_Blo;
#pragma unroll
    for (int it = 0; it < 4; it++) {
        int idx = it * 256 + tid;
        int r = idx >> 3, u = idx & 7;
        *(uint4*)(Ah + r * ASTR + u * 8) = w3h4[(c0 + r) * 8 + u];
        *(uint4*)(Al + r * ASTR + u * 8) = w3l4[(c0 + r) * 8 + u];
        *(uint4*)(Bh + r * ASTR + u * 8) = bh4[(q0 + r) * 8 + u];
        *(uint4*)(Bl + r * ASTR + u * 8) = bl4[(q0 + r) * 8 + u];
    }
    __syncthreads();

    int wid = tid >> 5, l = tid & 31;
    int wm = (wid & 3) * 32;
    int wn = (wid >> 2) * 64;
    int lr = l >> 2;
    int lc = (l & 3) * 2;

    float acc[2][8][4];
#pragma unroll
    for (int mi = 0; mi < 2; mi++)
#pragma unroll
        for (int ni = 0; ni < 8; ni++)
#pragma unroll
            for (int r = 0; r < 4; r++) acc[mi][ni][r] = 0.f;

    const __nv_bfloat16* Aterm[3] = {Ah, Ah, Al};
    const __nv_bfloat16* Bterm[3] = {Bh, Bl, Bh};
#pragma unroll
    for (int t = 0; t < 3; t++) {
        const __nv_bfloat16* A = Aterm[t];
        const __nv_bfloat16* B = Bterm[t];
#pragma unroll
        for (int k = 0; k < 4; k++) {
            int kb = k * 16;
            uint32_t af[2][4];
#pragma unroll
            for (int mi = 0; mi < 2; mi++) {
                int row = wm + mi * 16 + lr;
                af[mi][0] = *(const uint32_t*)(A + row * ASTR + kb + lc);
                af[mi][1] = *(const uint32_t*)(A + (row + 8) * ASTR + kb + lc);
                af[mi][2] = *(const uint32_t*)(A + row * ASTR + kb + 8 + lc);
                af[mi][3] = *(const uint32_t*)(A + (row + 8) * ASTR + kb + 8 + lc);
            }
#pragma unroll
            for (int ni = 0; ni < 8; ni++) {
                int nrow = wn + ni * 8 + lr;
                uint32_t b0 = *(const uint32_t*)(B + nrow * ASTR + kb + lc);
                uint32_t b1 = *(const uint32_t*)(B + nrow * ASTR + kb + 8 + lc);
                mma16816(acc[0][ni], af[0], b0, b1);
                mma16816(acc[1][ni], af[1], b0, b1);
            }
        }
    }

#pragma unroll
    for (int mi = 0; mi < 2; mi++) {
        int crow = c0 + wm + mi * 16 + lr;
        float bv0 = 8192.0f * b3[crow];
        float bv1 = 8192.0f * b3[crow + 8];
#pragma unroll
        for (int ni = 0; ni < 8; ni++) {
            int q = q0 + wn + ni * 8 + lc;
            int f = q >> 1;
            if (f < NF) {
                float2 v0 = make_float2(acc[mi][ni][0], acc[mi][ni][1]);
                float2 v1 = make_float2(acc[mi][ni][2], acc[mi][ni][3]);
                if (f == 0) { v0.x += bv0; v1.x += bv1; }
                d_Ff[(size_t)crow * NF + f] = v0;
                d_Ff[(size_t)(crow + 8) * NF + f] = v1;
            }
        }
    }
}

#define MMA_SMEM (4 * 128 * ASTR * sizeof(__nv_bfloat16))

// ---------------- frequency contraction (f-tiled, coalesced, register-blocked) ----------------
// Gf[b*32+o, f] = sum_i Xf[b*32+i, f] * Ff[o*32+i, f]
#define CFT 32    // freqs per block
#define CIC 4     // i per chunk
#define FSTR 33   // padded F row stride (float2)
#define GSTR 33   // padded output stride (float2)
#define CON_SMEM (256 * GSTR * sizeof(float2))   // 67584 B (>= chunk usage 5248 float2)

__global__ __launch_bounds__(512) void contract_kernel() {
    extern __shared__ float2 csm[];
    float2* Xs = csm;                  // [CIC][8][32]   : (ii*8+b)*32 + u
    float2* Fs = csm + CIC * 8 * 32;   // [CIC][32][FSTR]: (ii*32+o)*FSTR + u
    int tid = threadIdx.x;
    int f0 = blockIdx.x * CFT;
    int fi = tid >> 4;     // 0..31 freq within tile
    int s  = tid & 15;
    int bq = s >> 3;       // 0..1  (4 b each)
    int oq = s & 7;        // 0..7  (4 o each)

    float2 acc[4][4];
#pragma unroll
    for (int a = 0; a < 4; a++)
#pragma unroll
        for (int b = 0; b < 4; b++) acc[a][b] = make_float2(0.f, 0.f);

    for (int ic0 = 0; ic0 < 32; ic0 += CIC) {
        // X chunk: 32 rows x 32 f, row-contiguous global reads
        for (int idx = tid; idx < CIC * 8 * 32; idx += 512) {
            int u = idx & 31;
            int r = idx >> 5;             // ii*8 + b
            int ii = r >> 3, b = r & 7;
            int f = f0 + u;
            Xs[idx] = (f < NF) ? d_Xf[(size_t)(b * 32 + ic0 + ii) * NF + f]
                               : make_float2(0.f, 0.f);
        }
        // F chunk: 128 rows x 32 f
        for (int idx = tid; idx < CIC * 32 * 32; idx += 512) {
            int u = idx & 31;
            int r = idx >> 5;             // ii*32 + o
            int ii = r >> 5, o = r & 31;
            int f = f0 + u;
            Fs[r * FSTR + u] = (f < NF) ? d_Ff[(size_t)(o * 32 + ic0 + ii) * NF + f]
                                        : make_float2(0.f, 0.f);
        }
        __syncthreads();
#pragma unroll
        for (int ii = 0; ii < CIC; ii++) {
            float2 xv[4], fv[4];
#pragma unroll
            for (int bb = 0; bb < 4; bb++)
                xv[bb] = Xs[(ii * 8 + bq * 4 + bb) * 32 + fi];
#pragma unroll
            for (int oo = 0; oo < 4; oo++)
                fv[oo] = Fs[(ii * 32 + oq * 4 + oo) * FSTR + fi];
#pragma unroll
            for (int bb = 0; bb < 4; bb++)
#pragma unroll
                for (int oo = 0; oo < 4; oo++) {
                    float2 xvv = xv[bb], fvv = fv[oo];
                    acc[bb][oo].x = fmaf(xvv.x, fvv.x, acc[bb][oo].x);
                    acc[bb][oo].x = fmaf(-xvv.y, fvv.y, acc[bb][oo].x);
                    acc[bb][oo].y = fmaf(xvv.x, fvv.y, acc[bb][oo].y);
                    acc[bb][oo].y = fmaf(xvv.y, fvv.x, acc[bb][oo].y);
                }
        }
        __syncthreads();
    }
    // stage output in smem (padded), then write coalesced
    float2* Gs = csm;
#pragma unroll
    for (int bb = 0; bb < 4; bb++)
#pragma unroll
        for (int oo = 0; oo < 4; oo++) {
            int row = (bq * 4 + bb) * 32 + oq * 4 + oo;
            Gs[row * GSTR + fi] = acc[bb][oo];
        }
    __syncthreads();
    for (int idx = tid; idx < 256 * 32; idx += 512) {
        int u = idx & 31, row = idx >> 5;
        int f = f0 + u;
        if (f < NF) d_Gf[(size_t)row * NF + f] = Gs[row * GSTR + u];
    }
}

// ---------------- inverse rfft + bias ----------------
__global__ __launch_bounds__(512) void irfft_kernel(const float* __restrict__ bias,
                                                    float* __restrict__ out) {
    extern __shared__ float2 sm[];
    float2* A = sm;
    float2* Bp = sm + 4096;
    int tid = threadIdx.x;
    int row = blockIdx.x;
    const float2* G = d_Gf + (size_t)row * NF;
    for (int k = tid; k < MH; k += 512) {
        float2 Xk = G[k];
        float2 Xm = G[MH - k];
        float2 E = make_float2(0.5f * (Xk.x + Xm.x), 0.5f * (Xk.y - Xm.y));
        float2 D = make_float2(0.5f * (Xk.x - Xm.x), 0.5f * (Xk.y + Xm.y));
        float2 Wc = d_TW8[k];
        float2 Winv = make_float2(Wc.x, -Wc.y);
        float2 O = cmulf(Winv, D);
        A[k] = make_float2(E.x - O.y, -(E.y + O.x));
    }
    __syncthreads();
    fft4096(A, A, Bp, tid);
    float bo = bias[row & 31];
    float2* orow = (float2*)(out + (size_t)row * TLEN);
    const float inv = 1.0f / (float)MH;
    for (int k = tid; k < MH; k += 512) {
        float2 z = A[k];
        orow[k] = make_float2(fmaf(z.x, inv, bo), fmaf(-z.y, inv, bo));
    }
}

// ---------------- launch ----------------
extern "C" void kernel_launch(void* const* d_in, const int* in_sizes, int n_in,
                              void* d_out, int out_size) {
    const float* x    = (const float*)d_in[0];
    const float* w1   = (const float*)d_in[1];
    const float* b1   = (const float*)d_in[2];
    const float* w2   = (const float*)d_in[3];
    const float* b2   = (const float*)d_in[4];
    const float* w3   = (const float*)d_in[5];
    const float* b3   = (const float*)d_in[6];
    const float* bias = (const float*)d_in[7];
    float* out = (float*)d_out;

    cudaFuncSetAttribute(rfft_x_kernel, cudaFuncAttributeMaxDynamicSharedMemorySize, (int)FFT_SMEM);
    cudaFuncSetAttribute(rfft_h_kernel, cudaFuncAttributeMaxDynamicSharedMemorySize, (int)FFT_SMEM);
    cudaFuncSetAttribute(irfft_kernel, cudaFuncAttributeMaxDynamicSharedMemorySize, (int)FFT_SMEM);
    cudaFuncSetAttribute(gemm_mma_kernel, cudaFuncAttributeMaxDynamicSharedMemorySize, (int)MMA_SMEM);
    cudaFuncSetAttribute(contract_kernel, cudaFuncAttributeMaxDynamicSharedMemorySize, (int)CON_SMEM);

    init_tw_kernel<<<16, 512>>>();
    mlp_kernel<<<TLEN / 128, 128>>>(w1, b1, w2, b2);
    rfft_h_kernel<<<NHID, 512, FFT_SMEM>>>();
    prep_w3_kernel<<<NCOL / 64, 256>>>(w3);
    prep_B_kernel<<<QPAD / 128, 256>>>();
    gemm_mma_kernel<<<dim3(QPAD / 128, NCOL / 128), 256, MMA_SMEM>>>(b3);
    rfft_x_kernel<<<NB * NCIN, 512, FFT_SMEM>>>(x);
    contract_kernel<<<(NF + CFT - 1) / CFT, 512, CON_SMEM>>>();
    irfft_kernel<<<NB * NCOUT, 512, FFT_SMEM>>>(bias, out);
}

// round 13
// speedup vs baseline: 2.9708x; 1.0613x over previous
#include <cuda_runtime.h>
#include <cuda_bf16.h>
#include <cstdint>

#define TLEN 8192
#define MH   4096
#define NF   4097
#define NHID 64
#define NCIN 32
#define NCOUT 32
#define NB   8
#define NCOL (NCIN * NCOUT)
#define QPAD (65 * 128)

// ---------------- device global scratch (allocation-free) ----------------
__device__ float2 d_TW8[TLEN];                 // e^{-2*pi*i*k/8192}
__device__ float  d_H2T[NHID * TLEN];          // MLP hidden, transposed [j][t]
__device__ float2 d_Hf[NHID * NF];             // rfft of hidden rows
__device__ float2 d_Xf[(NB * NCIN) * NF];      // rfft(x) rows
__device__ float2 d_Ff[NCOL * NF];             // filter spectra [c][f]
__device__ float2 d_Gf[(NB * NCOUT) * NF];     // contracted spectrum rows
__device__ __nv_bfloat16 d_w3hi[NCOL * NHID];  // w3 transposed [c][j], hi part
__device__ __nv_bfloat16 d_w3lo[NCOL * NHID];  // lo part
__device__ __nv_bfloat16 d_Bhi[QPAD * NHID];   // Hr transposed [q][j], hi
__device__ __nv_bfloat16 d_Blo[QPAD * NHID];   // lo

__device__ __forceinline__ float2 cmulf(float2 a, float2 b) {
    return make_float2(fmaf(a.x, b.x, -a.y * b.y), fmaf(a.x, b.y, a.y * b.x));
}
__device__ __forceinline__ float2 cadd(float2 a, float2 b) { return make_float2(a.x + b.x, a.y + b.y); }
__device__ __forceinline__ float2 csub(float2 a, float2 b) { return make_float2(a.x - b.x, a.y - b.y); }
__device__ __forceinline__ float2 mulnegi(float2 a) { return make_float2(a.y, -a.x); }

#define PADIDX(a) ((a) + ((a) >> 3))

// ---------------- twiddle init ----------------
__global__ void init_tw_kernel() {
    int k = blockIdx.x * blockDim.x + threadIdx.x;
    if (k < TLEN) {
        double a = -2.0 * 3.14159265358979323846 * (double)k / (double)TLEN;
        d_TW8[k] = make_float2((float)cos(a), (float)sin(a));
    }
}

// ---------------- 8-point DFT in registers ----------------
__device__ __forceinline__ void fft8(const float2 c[8], float2 d[8]) {
    const float S = 0.70710678118654752440f;
    float2 a0 = cadd(c[0], c[4]), a1 = cadd(c[1], c[5]);
    float2 a2 = cadd(c[2], c[6]), a3 = cadd(c[3], c[7]);
    float2 b0 = csub(c[0], c[4]);
    float2 t1 = csub(c[1], c[5]);
    float2 b1 = make_float2(S * (t1.x + t1.y), S * (t1.y - t1.x));
    float2 t2 = csub(c[2], c[6]);
    float2 b2 = mulnegi(t2);
    float2 t3 = csub(c[3], c[7]);
    float2 b3 = make_float2(S * (t3.y - t3.x), -S * (t3.x + t3.y));
    float2 p0 = cadd(a0, a2), q0 = csub(a0, a2);
    float2 p1 = cadd(a1, a3), q1 = mulnegi(csub(a1, a3));
    d[0] = cadd(p0, p1); d[4] = csub(p0, p1);
    d[2] = cadd(q0, q1); d[6] = csub(q0, q1);
    float2 r0 = cadd(b0, b2), s0 = csub(b0, b2);
    float2 r1 = cadd(b1, b3), s1 = mulnegi(csub(b1, b3));
    d[1] = cadd(r0, r1); d[5] = csub(r0, r1);
    d[3] = cadd(s0, s1); d[7] = csub(s0, s1);
}

template <int L, int M, int SP, int DP>
__device__ __forceinline__ void stage8(const float2* __restrict__ src,
                                       float2* __restrict__ dst, int tid) {
    int j = tid / M;
    int k = tid - j * M;
    float2 c[8], d[8];
#pragma unroll
    for (int i = 0; i < 8; i++) {
        int a = tid + i * 512;
        c[i] = src[SP ? PADIDX(a) : a];
    }
    fft8(c, d);
    if (L > 1) {
        int tstep = j * (1024 / L);
        float2 w = d_TW8[tstep];
        float2 wt = w;
        d[1] = cmulf(d[1], w);
#pragma unroll
        for (int t = 2; t < 8; t++) {
            wt = cmulf(wt, w);
            d[t] = cmulf(d[t], wt);
        }
    }
    int base = k + M * 8 * j;
#pragma unroll
    for (int t = 0; t < 8; t++) {
        int a = base + M * t;
        dst[DP ? PADIDX(a) : a] = d[t];
    }
}

__device__ void fft4096(const float2* __restrict__ src, float2* A, float2* Bp, int tid) {
    stage8<512, 1, 0, 1>(src, Bp, tid);
    __syncthreads();
    stage8<64, 8, 1, 0>(Bp, A, tid);
    __syncthreads();
    stage8<8, 64, 0, 1>(A, Bp, tid);
    __syncthreads();
    stage8<1, 512, 1, 0>(Bp, A, tid);
    __syncthreads();
}

__device__ void rfft_post(const float2* A, float2* out, int tid) {
    for (int k = tid; k <= MH / 2; k += 512) {
        float2 Zk = A[k];
        float2 Zm = A[(MH - k) & (MH - 1)];
        float2 E = make_float2(0.5f * (Zk.x + Zm.x), 0.5f * (Zk.y - Zm.y));
        float2 O = make_float2(0.5f * (Zk.y + Zm.y), 0.5f * (Zm.x - Zk.x));
        float2 WO = cmulf(d_TW8[k], O);
        out[k]      = make_float2(E.x + WO.x, E.y + WO.y);
        out[MH - k] = make_float2(E.x - WO.x, -(E.y - WO.y));
    }
}

__device__ void rfft_row(const float* __restrict__ src_row, float2* __restrict__ dst_row,
                         float2* A, float2* Bp, int tid) {
    fft4096((const float2*)src_row, A, Bp, tid);
    rfft_post(A, dst_row, tid);
}

#define FFT_SMEM ((4096 + 4608) * sizeof(float2))

// ---------------- MLP hidden ----------------
__global__ void mlp_kernel(const float* __restrict__ w1, const float* __restrict__ b1,
                           const float* __restrict__ w2, const float* __restrict__ b2) {
    __shared__ float w2s[NHID * NHID];
    __shared__ float w1s[NHID], b1s[NHID], b2s[NHID];
    int tid = threadIdx.x;
    for (int i = tid; i < NHID * NHID; i += blockDim.x) w2s[i] = w2[i];
    if (tid < NHID) { w1s[tid] = w1[tid]; b1s[tid] = b1[tid]; b2s[tid] = b2[tid]; }
    __syncthreads();
    int t = blockIdx.x * blockDim.x + tid;
    float pos = (float)t / 8191.0f;
    float h1[NHID];
#pragma unroll
    for (int k = 0; k < NHID; k++) {
        float v = fmaf(pos, w1s[k], b1s[k]);
        h1[k] = 0.5f * v * (1.0f + erff(v * 0.70710678118654752f));
    }
    for (int j = 0; j < NHID; j++) {
        float acc = b2s[j];
#pragma unroll
        for (int k = 0; k < NHID; k++) acc = fmaf(h1[k], w2s[k * NHID + j], acc);
        float g = 0.5f * acc * (1.0f + erff(acc * 0.70710678118654752f));
        d_H2T[j * TLEN + t] = g;
    }
}

// ---------------- forward rfft kernels ----------------
__global__ __launch_bounds__(512) void rfft_x_kernel(const float* __restrict__ x) {
    extern __shared__ float2 sm[];
    int row = blockIdx.x;
    rfft_row(x + (size_t)row * TLEN, d_Xf + (size_t)row * NF, sm, sm + 4096, threadIdx.x);
}

__global__ __launch_bounds__(512) void rfft_h_kernel() {
    extern __shared__ float2 sm[];
    int row = blockIdx.x;
    rfft_row(d_H2T + (size_t)row * TLEN, d_Hf + (size_t)row * NF, sm, sm + 4096, threadIdx.x);
}

// ---------------- prep: w3 -> [c][j] bf16 hi/lo (coalesced reads, scattered L2 writes) ----------------
__global__ void prep_w3_kernel(const float* __restrict__ w3) {
    int idx = blockIdx.x * 256 + threadIdx.x;  // 65536
    int j = idx >> 10, c = idx & 1023;         // read w3[j*1024+c] coalesced
    float x = w3[idx];
    __nv_bfloat16 h = __float2bfloat16(x);
    int o = c * 64 + j;
    d_w3hi[o] = h;
    d_w3lo[o] = __float2bfloat16(x - __bfloat162float(h));
}

// ---------------- prep: Hf -> [q][j] bf16 hi/lo (smem transpose) ----------------
__global__ void prep_B_kernel() {
    __shared__ float2 sf[64][65];
    int tid = threadIdx.x;
    int q0 = blockIdx.x * 128;
    int f0 = q0 >> 1;
    for (int idx = tid; idx < 64 * 64; idx += 256) {
        int j = idx >> 6, fi = idx & 63;
        int f = f0 + fi;
        sf[j][fi] = (f < NF) ? d_Hf[(size_t)j * NF + f] : make_float2(0.f, 0.f);
    }
    __syncthreads();
    for (int idx = tid; idx < 128 * 64; idx += 256) {
        int q = idx >> 6, j = idx & 63;
        float2 v = sf[j][q >> 1];
        float x = (q & 1) ? v.y : v.x;
        __nv_bfloat16 h = __float2bfloat16(x);
        int o = (q0 + q) * 64 + j;
        d_Bhi[o] = h;
        d_Blo[o] = __float2bfloat16(x - __bfloat162float(h));
    }
}

// ---------------- HMMA frequency GEMM (mma.sync, baseline PTX) ----------------
#define ASTR 72

__device__ __forceinline__ void mma16816(float c[4], const uint32_t a[4],
                                         uint32_t b0, uint32_t b1) {
    asm volatile(
        "mma.sync.aligned.m16n8k16.row.col.f32.bf16.bf16.f32 "
        "{%0,%1,%2,%3}, {%4,%5,%6,%7}, {%8,%9}, {%0,%1,%2,%3};"
        : "+f"(c[0]), "+f"(c[1]), "+f"(c[2]), "+f"(c[3])
        : "r"(a[0]), "r"(a[1]), "r"(a[2]), "r"(a[3]), "r"(b0), "r"(b1));
}

__global__ __launch_bounds__(256) void gemm_mma_kernel(const float* __restrict__ b3) {
    extern __shared__ __nv_bfloat16 ms[];
    __nv_bfloat16* Ah = ms;                    // [128][ASTR]
    __nv_bfloat16* Al = Ah + 128 * ASTR;
    __nv_bfloat16* Bh = Al + 128 * ASTR;
    __nv_bfloat16* Bl = Bh + 128 * ASTR;
    int tid = threadIdx.x;
    int q0 = blockIdx.x * 128;
    int c0 = blockIdx.y * 128;

    const uint4* w3h4 = (const uint4*)d_w3hi;
    const uint4* w3l4 = (const uint4*)d_w3lo;
    const uint4* bh4  = (const uint4*)d_Bhi;
    const uint4* bl4  = (const uint4*)d_Blo;
#pragma unroll
    for (int it = 0; it < 4; it++) {
        int idx = it * 256 + tid;
        int r = idx >> 3, u = idx & 7;
        *(uint4*)(Ah + r * ASTR + u * 8) = w3h4[(c0 + r) * 8 + u];
        *(uint4*)(Al + r * ASTR + u * 8) = w3l4[(c0 + r) * 8 + u];
        *(uint4*)(Bh + r * ASTR + u * 8) = bh4[(q0 + r) * 8 + u];
        *(uint4*)(Bl + r * ASTR + u * 8) = bl4[(q0 + r) * 8 + u];
    }
    __syncthreads();

    int wid = tid >> 5, l = tid & 31;
    int wm = (wid & 3) * 32;
    int wn = (wid >> 2) * 64;
    int lr = l >> 2;
    int lc = (l & 3) * 2;

    float acc[2][8][4];
#pragma unroll
    for (int mi = 0; mi < 2; mi++)
#pragma unroll
        for (int ni = 0; ni < 8; ni++)
#pragma unroll
            for (int r = 0; r < 4; r++) acc[mi][ni][r] = 0.f;

    const __nv_bfloat16* Aterm[3] = {Ah, Ah, Al};
    const __nv_bfloat16* Bterm[3] = {Bh, Bl, Bh};
#pragma unroll
    for (int t = 0; t < 3; t++) {
        const __nv_bfloat16* A = Aterm[t];
        const __nv_bfloat16* B = Bterm[t];
#pragma unroll
        for (int k = 0; k < 4; k++) {
            int kb = k * 16;
            uint32_t af[2][4];
#pragma unroll
            for (int mi = 0; mi < 2; mi++) {
                int row = wm + mi * 16 + lr;
                af[mi][0] = *(const uint32_t*)(A + row * ASTR + kb + lc);
                af[mi][1] = *(const uint32_t*)(A + (row + 8) * ASTR + kb + lc);
                af[mi][2] = *(const uint32_t*)(A + row * ASTR + kb + 8 + lc);
                af[mi][3] = *(const uint32_t*)(A + (row + 8) * ASTR + kb + 8 + lc);
            }
#pragma unroll
            for (int ni = 0; ni < 8; ni++) {
                int nrow = wn + ni * 8 + lr;
                uint32_t b0 = *(const uint32_t*)(B + nrow * ASTR + kb + lc);
                uint32_t b1 = *(const uint32_t*)(B + nrow * ASTR + kb + 8 + lc);
                mma16816(acc[0][ni], af[0], b0, b1);
                mma16816(acc[1][ni], af[1], b0, b1);
            }
        }
    }

#pragma unroll
    for (int mi = 0; mi < 2; mi++) {
        int crow = c0 + wm + mi * 16 + lr;
        float bv0 = 8192.0f * b3[crow];
        float bv1 = 8192.0f * b3[crow + 8];
#pragma unroll
        for (int ni = 0; ni < 8; ni++) {
            int q = q0 + wn + ni * 8 + lc;
            int f = q >> 1;
            if (f < NF) {
                float2 v0 = make_float2(acc[mi][ni][0], acc[mi][ni][1]);
                float2 v1 = make_float2(acc[mi][ni][2], acc[mi][ni][3]);
                if (f == 0) { v0.x += bv0; v1.x += bv1; }
                d_Ff[(size_t)crow * NF + f] = v0;
                d_Ff[(size_t)(crow + 8) * NF + f] = v1;
            }
        }
    }
}

#define MMA_SMEM (4 * 128 * ASTR * sizeof(__nv_bfloat16))

// ---------------- frequency contraction (f-tiled, coalesced, register-blocked) ----------------
#define CFT 32
#define CIC 4
#define FSTR 33
#define GSTR 33
#define CON_SMEM (256 * GSTR * sizeof(float2))

__global__ __launch_bounds__(512) void contract_kernel() {
    extern __shared__ float2 csm[];
    float2* Xs = csm;
    float2* Fs = csm + CIC * 8 * 32;
    int tid = threadIdx.x;
    int f0 = blockIdx.x * CFT;
    int fi = tid >> 4;
    int s  = tid & 15;
    int bq = s >> 3;
    int oq = s & 7;

    float2 acc[4][4];
#pragma unroll
    for (int a = 0; a < 4; a++)
#pragma unroll
        for (int b = 0; b < 4; b++) acc[a][b] = make_float2(0.f, 0.f);

    for (int ic0 = 0; ic0 < 32; ic0 += CIC) {
        for (int idx = tid; idx < CIC * 8 * 32; idx += 512) {
            int u = idx & 31;
            int r = idx >> 5;
            int ii = r >> 3, b = r & 7;
            int f = f0 + u;
            Xs[idx] = (f < NF) ? d_Xf[(size_t)(b * 32 + ic0 + ii) * NF + f]
                               : make_float2(0.f, 0.f);
        }
        for (int idx = tid; idx < CIC * 32 * 32; idx += 512) {
            int u = idx & 31;
            int r = idx >> 5;
            int ii = r >> 5, o = r & 31;
            int f = f0 + u;
            Fs[r * FSTR + u] = (f < NF) ? d_Ff[(size_t)(o * 32 + ic0 + ii) * NF + f]
                                        : make_float2(0.f, 0.f);
        }
        __syncthreads();
#pragma unroll
        for (int ii = 0; ii < CIC; ii++) {
            float2 xv[4], fv[4];
#pragma unroll
            for (int bb = 0; bb < 4; bb++)
                xv[bb] = Xs[(ii * 8 + bq * 4 + bb) * 32 + fi];
#pragma unroll
            for (int oo = 0; oo < 4; oo++)
                fv[oo] = Fs[(ii * 32 + oq * 4 + oo) * FSTR + fi];
#pragma unroll
            for (int bb = 0; bb < 4; bb++)
#pragma unroll
                for (int oo = 0; oo < 4; oo++) {
                    float2 xvv = xv[bb], fvv = fv[oo];
                    acc[bb][oo].x = fmaf(xvv.x, fvv.x, acc[bb][oo].x);
                    acc[bb][oo].x = fmaf(-xvv.y, fvv.y, acc[bb][oo].x);
                    acc[bb][oo].y = fmaf(xvv.x, fvv.y, acc[bb][oo].y);
                    acc[bb][oo].y = fmaf(xvv.y, fvv.x, acc[bb][oo].y);
                }
        }
        __syncthreads();
    }
    float2* Gs = csm;
#pragma unroll
    for (int bb = 0; bb < 4; bb++)
#pragma unroll
        for (int oo = 0; oo < 4; oo++) {
            int row = (bq * 4 + bb) * 32 + oq * 4 + oo;
            Gs[row * GSTR + fi] = acc[bb][oo];
        }
    __syncthreads();
    for (int idx = tid; idx < 256 * 32; idx += 512) {
        int u = idx & 31, row = idx >> 5;
        int f = f0 + u;
        if (f < NF) d_Gf[(size_t)row * NF + f] = Gs[row * GSTR + u];
    }
}

// ---------------- inverse rfft + bias ----------------
__global__ __launch_bounds__(512) void irfft_kernel(const float* __restrict__ bias,
                                                    float* __restrict__ out) {
    extern __shared__ float2 sm[];
    float2* A = sm;
    float2* Bp = sm + 4096;
    int tid = threadIdx.x;
    int row = blockIdx.x;
    const float2* G = d_Gf + (size_t)row * NF;
    for (int k = tid; k < MH; k += 512) {
        float2 Xk = G[k];
        float2 Xm = G[MH - k];
        float2 E = make_float2(0.5f * (Xk.x + Xm.x), 0.5f * (Xk.y - Xm.y));
        float2 D = make_float2(0.5f * (Xk.x - Xm.x), 0.5f * (Xk.y + Xm.y));
        float2 Wc = d_TW8[k];
        float2 Winv = make_float2(Wc.x, -Wc.y);
        float2 O = cmulf(Winv, D);
        A[k] = make_float2(E.x - O.y, -(E.y + O.x));
    }
    __syncthreads();
    fft4096(A, A, Bp, tid);
    float bo = bias[row & 31];
    float2* orow = (float2*)(out + (size_t)row * TLEN);
    const float inv = 1.0f / (float)MH;
    for (int k = tid; k < MH; k += 512) {
        float2 z = A[k];
        orow[k] = make_float2(fmaf(z.x, inv, bo), fmaf(-z.y, inv, bo));
    }
}

// ---------------- launch ----------------
extern "C" void kernel_launch(void* const* d_in, const int* in_sizes, int n_in,
                              void* d_out, int out_size) {
    const float* x    = (const float*)d_in[0];
    const float* w1   = (const float*)d_in[1];
    const float* b1   = (const float*)d_in[2];
    const float* w2   = (const float*)d_in[3];
    const float* b2   = (const float*)d_in[4];
    const float* w3   = (const float*)d_in[5];
    const float* b3   = (const float*)d_in[6];
    const float* bias = (const float*)d_in[7];
    float* out = (float*)d_out;

    cudaFuncSetAttribute(rfft_x_kernel, cudaFuncAttributeMaxDynamicSharedMemorySize, (int)FFT_SMEM);
    cudaFuncSetAttribute(rfft_h_kernel, cudaFuncAttributeMaxDynamicSharedMemorySize, (int)FFT_SMEM);
    cudaFuncSetAttribute(irfft_kernel, cudaFuncAttributeMaxDynamicSharedMemorySize, (int)FFT_SMEM);
    cudaFuncSetAttribute(gemm_mma_kernel, cudaFuncAttributeMaxDynamicSharedMemorySize, (int)MMA_SMEM);
    cudaFuncSetAttribute(contract_kernel, cudaFuncAttributeMaxDynamicSharedMemorySize, (int)CON_SMEM);

    // Fork a side stream so rfft_x overlaps the MLP->GEMM chain.
    cudaStream_t s2;
    cudaEvent_t evFork, evJoin;
    cudaStreamCreateWithFlags(&s2, cudaStreamNonBlocking);
    cudaEventCreateWithFlags(&evFork, cudaEventDisableTiming);
    cudaEventCreateWithFlags(&evJoin, cudaEventDisableTiming);

    init_tw_kernel<<<16, 512>>>();
    cudaEventRecord(evFork, 0);
    cudaStreamWaitEvent(s2, evFork, 0);
    rfft_x_kernel<<<NB * NCIN, 512, FFT_SMEM, s2>>>(x);
    cudaEventRecord(evJoin, s2);

    mlp_kernel<<<TLEN / 128, 128>>>(w1, b1, w2, b2);
    rfft_h_kernel<<<NHID, 512, FFT_SMEM>>>();
    prep_w3_kernel<<<NCOL * NHID / 256, 256>>>(w3);
    prep_B_kernel<<<QPAD / 128, 256>>>();
    gemm_mma_kernel<<<dim3(QPAD / 128, NCOL / 128), 256, MMA_SMEM>>>(b3);

    cudaStreamWaitEvent(0, evJoin, 0);
    contract_kernel<<<(NF + CFT - 1) / CFT, 512, CON_SMEM>>>();
    irfft_kernel<<<NB * NCOUT, 512, FFT_SMEM>>>(bias, out);
}